// round 11
// baseline (speedup 1.0000x reference)
#include <cuda_runtime.h>
#include <cuda_bf16.h>
#include <math.h>
#include <string.h>

#define N_NODES   100000
#define N_EDGES   1600000
#define NF        128
#define N_GRAPHS  1024

// ---------------- scratch (static device globals; no allocation) ----------------
__device__ float g_xw [N_NODES * NF];   // GEMM output (per-layer)
__device__ float g_h1 [N_NODES * NF];   // hidden ping
__device__ float g_h2 [N_NODES * NF];   // hidden pong
__device__ int   g_cnt   [N_NODES];
__device__ int   g_rowptr[N_NODES + 1];
__device__ int   g_cursor[N_NODES];
__device__ float g_isq   [N_NODES];     // deg^{-1/2}
__device__ float g_invdeg[N_NODES];     // 1/deg  (self-loop norm)
__device__ int   g_src   [N_EDGES];     // CSR (by dst) src node ids
__device__ float g_enorm [N_EDGES];     // per-edge norm
__device__ int   g_gstart[N_GRAPHS + 1];
__device__ int   g_is64;                // 1 if index inputs are int64, 0 if int32

// ---------------- dtype detection ----------------
__global__ void detect_dtype_kernel(const int* __restrict__ ei32) {
    if (threadIdx.x != 0 || blockIdx.x != 0) return;
    int is64 = 1;
    #pragma unroll 1
    for (int i = 0; i < 128; i++) {
        if (ei32[2 * i + 1] != 0) { is64 = 0; break; }
    }
    g_is64 = is64;
}

__device__ __forceinline__ int load_idx(const void* p, long long i, bool is64) {
    return is64 ? (int)((const long long*)p)[i] : ((const int*)p)[i];
}

// ---------------- CSR build ----------------
__global__ void zero_cnt_kernel() {
    int i = blockIdx.x * blockDim.x + threadIdx.x;
    if (i < N_NODES) g_cnt[i] = 0;
}

__global__ void count_deg_kernel(const void* __restrict__ ei) {
    bool is64 = (g_is64 != 0);
    int stride = gridDim.x * blockDim.x;
    for (int e = blockIdx.x * blockDim.x + threadIdx.x; e < N_EDGES; e += stride) {
        int dst = load_idx(ei, (long long)N_EDGES + e, is64);
        if ((unsigned)dst < (unsigned)N_NODES)
            atomicAdd(&g_cnt[dst], 1);
    }
}

__global__ void compute_isq_kernel() {
    int i = blockIdx.x * blockDim.x + threadIdx.x;
    if (i >= N_NODES) return;
    float deg = (float)(g_cnt[i] + 1);      // +1 self loop; always >= 1
    g_isq[i]    = rsqrtf(deg);
    g_invdeg[i] = 1.0f / deg;
}

// single-block exclusive scan of g_cnt -> g_rowptr / g_cursor
__global__ void scan_kernel() {
    __shared__ int wsum[32];
    __shared__ int carry_s;
    int tid = threadIdx.x, lane = tid & 31, wid = tid >> 5;
    if (tid == 0) carry_s = 0;
    __syncthreads();
    for (int base = 0; base < N_NODES; base += 4096) {
        int i0 = base + tid * 4;
        int v0 = 0, v1 = 0, v2 = 0, v3 = 0;
        if (i0 + 3 < N_NODES) {
            int4 t = *(const int4*)&g_cnt[i0];
            v0 = t.x; v1 = t.y; v2 = t.z; v3 = t.w;
        } else {
            if (i0     < N_NODES) v0 = g_cnt[i0];
            if (i0 + 1 < N_NODES) v1 = g_cnt[i0 + 1];
            if (i0 + 2 < N_NODES) v2 = g_cnt[i0 + 2];
            if (i0 + 3 < N_NODES) v3 = g_cnt[i0 + 3];
        }
        int ts = v0 + v1 + v2 + v3;
        int x = ts;
        #pragma unroll
        for (int o = 1; o < 32; o <<= 1) {
            int y = __shfl_up_sync(0xffffffffu, x, o);
            if (lane >= o) x += y;
        }
        if (lane == 31) wsum[wid] = x;
        __syncthreads();
        if (wid == 0) {
            int s = wsum[lane];
            #pragma unroll
            for (int o = 1; o < 32; o <<= 1) {
                int y = __shfl_up_sync(0xffffffffu, s, o);
                if (lane >= o) s += y;
            }
            wsum[lane] = s;
        }
        __syncthreads();
        int wexcl = wid ? wsum[wid - 1] : 0;
        int excl = x - ts + wexcl + carry_s;
        int e0 = excl, e1 = e0 + v0, e2 = e1 + v1, e3 = e2 + v2;
        if (i0     < N_NODES) { g_rowptr[i0]     = e0; g_cursor[i0]     = e0; }
        if (i0 + 1 < N_NODES) { g_rowptr[i0 + 1] = e1; g_cursor[i0 + 1] = e1; }
        if (i0 + 2 < N_NODES) { g_rowptr[i0 + 2] = e2; g_cursor[i0 + 2] = e2; }
        if (i0 + 3 < N_NODES) { g_rowptr[i0 + 3] = e3; g_cursor[i0 + 3] = e3; }
        __syncthreads();
        if (tid == 1023) carry_s += wsum[31];
        __syncthreads();
    }
    if (threadIdx.x == 0) g_rowptr[N_NODES] = carry_s;
}

__global__ void scatter_edges_kernel(const void* __restrict__ ei) {
    bool is64 = (g_is64 != 0);
    int stride = gridDim.x * blockDim.x;
    for (int e = blockIdx.x * blockDim.x + threadIdx.x; e < N_EDGES; e += stride) {
        int src = load_idx(ei, e, is64);
        int dst = load_idx(ei, (long long)N_EDGES + e, is64);
        if ((unsigned)src >= (unsigned)N_NODES) continue;
        if ((unsigned)dst >= (unsigned)N_NODES) continue;
        int pos = atomicAdd(&g_cursor[dst], 1);
        if ((unsigned)pos < (unsigned)N_EDGES) {
            g_src[pos]   = src;
            g_enorm[pos] = g_isq[src] * g_isq[dst];
        }
    }
}

// ---------------- GEMM: g_xw[M x 128] = A[M x 128] @ W[128 x 128] ----------------
// Packed-f32x2 (FFMA2) version: lanes of the 64-bit packed reg carry even/odd-k
// partial sums; horizontal add in the epilogue. Exact fp32 math (reassociated).
// A pairs are contiguous in As rows; W pairs come from a transposed chunk
// Wt[n][kk] with 18-float padded rows (even offsets -> 8B-aligned LDS.64).
// selA: 0 -> external x, 1 -> g_h1, 2 -> g_h2.  Output always g_xw.
__global__ __launch_bounds__(256) void gemm128_kernel(
    const float* __restrict__ xin, int selA, const float* __restrict__ W, int M)
{
    __shared__ __align__(16) float As[64 * 128];     // 32 KB
    __shared__ __align__(16) float Wt[128 * 18];     // 9 KB (16-k chunk, transposed, padded)
    const float* A = (selA == 0) ? xin : (selA == 1 ? g_h1 : g_h2);
    int tid  = threadIdx.x;
    int lane = tid & 31;
    int tm   = (tid >> 5) * 8;           // 8 warps x 8 rows = 64 rows
    int m0   = blockIdx.x * 64;

    // load A tile (64 rows x 128 cols), float4-wide, coalesced
    #pragma unroll
    for (int i = 0; i < 8; i++) {
        int f4 = tid + i * 256;                 // 2048 float4 total
        int r = f4 >> 5;
        int c = (f4 & 31) * 4;
        int row = m0 + r;
        float4 v = make_float4(0.f, 0.f, 0.f, 0.f);
        if (row < M) v = *(const float4*)&A[row * NF + c];
        *(float4*)&As[r * NF + c] = v;
    }

    unsigned long long acc[8][4];
    #pragma unroll
    for (int j = 0; j < 8; j++)
        #pragma unroll
        for (int c = 0; c < 4; c++) acc[j][c] = 0ull;

    #pragma unroll 1
    for (int kc = 0; kc < 8; kc++) {            // eight 16-row chunks of W
        __syncthreads();
        // load W chunk transposed: Wt[n][kk] = W[kc*16+kk][n]
        #pragma unroll
        for (int i = 0; i < 2; i++) {
            int f4 = tid + i * 256;             // 512 float4 = 16*128 floats
            int kk = f4 >> 5;                   // 0..15
            int c  = (f4 & 31) * 4;             // 0..124
            float4 w = *(const float4*)&W[(kc * 16 + kk) * NF + c];
            Wt[(c + 0) * 18 + kk] = w.x;
            Wt[(c + 1) * 18 + kk] = w.y;
            Wt[(c + 2) * 18 + kk] = w.z;
            Wt[(c + 3) * 18 + kk] = w.w;
        }
        __syncthreads();

        #pragma unroll
        for (int kp = 0; kp < 8; kp++) {        // 8 k-pairs per chunk
            int kk = kp * 2;
            int kg = kc * 16 + kk;
            unsigned long long w2[4];
            #pragma unroll
            for (int c = 0; c < 4; c++)         // col n = lane + 32c
                w2[c] = *(const unsigned long long*)&Wt[(lane + 32 * c) * 18 + kk];
            #pragma unroll
            for (int j = 0; j < 8; j++) {
                unsigned long long a2 =
                    *(const unsigned long long*)&As[(tm + j) * NF + kg]; // warp-uniform
                #pragma unroll
                for (int c = 0; c < 4; c++)
                    asm("fma.rn.f32x2 %0, %1, %2, %0;"
                        : "+l"(acc[j][c]) : "l"(a2), "l"(w2[c]));
            }
        }
    }

    #pragma unroll
    for (int j = 0; j < 8; j++) {
        int row = m0 + tm + j;
        if (row < M) {
            #pragma unroll
            for (int c = 0; c < 4; c++) {
                float2 v;
                memcpy(&v, &acc[j][c], 8);
                g_xw[row * NF + lane + 32 * c] = v.x + v.y;   // coalesced scalar stores
            }
        }
    }
}

// ---------------- aggregation: warp per node, CSR gather, +self, +bias, relu ----
// selOut: 1 -> g_h1, 2 -> g_h2
__global__ __launch_bounds__(256) void aggregate_kernel(
    const float* __restrict__ bias, int selOut)
{
    int node = (blockIdx.x * blockDim.x + threadIdx.x) >> 5;
    if (node >= N_NODES) return;
    float* out = (selOut == 1) ? g_h1 : g_h2;
    int lane = threadIdx.x & 31;
    int beg = g_rowptr[node];
    int end = g_rowptr[node + 1];
    float ax = 0.f, ay = 0.f, az = 0.f, aw = 0.f;
    int col = lane * 4;
    for (int e = beg; e < end; e++) {
        int   s = g_src[e];
        float w = g_enorm[e];
        float4 v = *(const float4*)&g_xw[s * NF + col];
        ax += w * v.x; ay += w * v.y; az += w * v.z; aw += w * v.w;
    }
    // self loop
    float sd = g_invdeg[node];
    float4 vs = *(const float4*)&g_xw[node * NF + col];
    ax += sd * vs.x; ay += sd * vs.y; az += sd * vs.z; aw += sd * vs.w;
    // bias + relu
    float4 b = *(const float4*)&bias[col];
    ax = fmaxf(ax + b.x, 0.f);
    ay = fmaxf(ay + b.y, 0.f);
    az = fmaxf(az + b.z, 0.f);
    aw = fmaxf(aw + b.w, 0.f);
    *(float4*)&out[node * NF + col] = make_float4(ax, ay, az, aw);
}

// ---------------- pooling + FC ----------------
__global__ void graph_bounds_kernel(const void* __restrict__ batch) {
    bool is64 = (g_is64 != 0);
    int g = blockIdx.x * blockDim.x + threadIdx.x;
    if (g > N_GRAPHS) return;
    int lo = 0, hi = N_NODES;
    while (lo < hi) {
        int mid = (lo + hi) >> 1;
        int bv = load_idx(batch, mid, is64);
        if (bv < g) lo = mid + 1; else hi = mid;
    }
    g_gstart[g] = lo;
}

__global__ void pool_fc_kernel(const float* __restrict__ Wfc,
                               const float* __restrict__ bfc,
                               float* __restrict__ out)
{
    __shared__ float red[128];
    int g = blockIdx.x;
    int t = threadIdx.x;            // 128
    int beg = g_gstart[g], end = g_gstart[g + 1];
    if (beg < 0) beg = 0;
    if (end > N_NODES) end = N_NODES;
    float s = 0.f;
    for (int n = beg; n < end; n++) s += g_h1[n * NF + t];
    float cnt = (float)(end - beg);
    float mean = (cnt > 0.f) ? (s / cnt) : 0.f;
    red[t] = mean * Wfc[t];
    __syncthreads();
    #pragma unroll
    for (int o = 64; o > 0; o >>= 1) {
        if (t < o) red[t] += red[t + o];
        __syncthreads();
    }
    if (t == 0) out[g] = red[0] + bfc[0];
}

// ---------------- launch ----------------
extern "C" void kernel_launch(void* const* d_in, const int* in_sizes, int n_in,
                              void* d_out, int out_size) {
    const float* x     = (const float*)d_in[0];
    const void*  ei    = d_in[1];
    const void*  batch = d_in[2];
    const float* W1  = (const float*)d_in[3];
    const float* b1  = (const float*)d_in[4];
    const float* W2  = (const float*)d_in[5];
    const float* b2  = (const float*)d_in[6];
    const float* W3  = (const float*)d_in[7];
    const float* b3  = (const float*)d_in[8];
    const float* Wfc = (const float*)d_in[9];
    const float* bfc = (const float*)d_in[10];
    float* out = (float*)d_out;

    // dtype probe (int64 vs int32 index buffers), then CSR build
    detect_dtype_kernel<<<1, 32>>>((const int*)ei);
    zero_cnt_kernel<<<(N_NODES + 255) / 256, 256>>>();
    count_deg_kernel<<<2048, 256>>>(ei);
    compute_isq_kernel<<<(N_NODES + 255) / 256, 256>>>();
    scan_kernel<<<1, 1024>>>();
    scatter_edges_kernel<<<2048, 256>>>(ei);

    const int GEMM_BLOCKS = (N_NODES + 63) / 64;
    const int AGG_BLOCKS  = (N_NODES * 32 + 255) / 256;

    // layer 1
    gemm128_kernel<<<GEMM_BLOCKS, 256>>>(x, 0, W1, N_NODES);
    aggregate_kernel<<<AGG_BLOCKS, 256>>>(b1, 1);
    // layer 2
    gemm128_kernel<<<GEMM_BLOCKS, 256>>>(x, 1, W2, N_NODES);
    aggregate_kernel<<<AGG_BLOCKS, 256>>>(b2, 2);
    // layer 3
    gemm128_kernel<<<GEMM_BLOCKS, 256>>>(x, 2, W3, N_NODES);
    aggregate_kernel<<<AGG_BLOCKS, 256>>>(b3, 1);

    // pool + fc
    graph_bounds_kernel<<<(N_GRAPHS + 1 + 255) / 256, 256>>>(batch);
    pool_fc_kernel<<<N_GRAPHS, 128>>>(Wfc, bfc, out);
}

// round 12
// speedup vs baseline: 1.3431x; 1.3431x over previous
#include <cuda_runtime.h>
#include <cuda_bf16.h>
#include <math.h>

#define N_NODES   100000
#define N_EDGES   1600000
#define NF        128
#define N_GRAPHS  1024

// ---------------- scratch (static device globals; no allocation) ----------------
__device__ float g_xw [N_NODES * NF];           // GEMM output (per-layer, fp32)
__device__ float g_h1 [N_NODES * NF];           // layer-3 hidden (fp32, for pool)
__device__ __nv_bfloat16 g_Ah[N_NODES * NF];    // GEMM A input, bf16 hi
__device__ __nv_bfloat16 g_Al[N_NODES * NF];    // GEMM A input, bf16 lo
__device__ __nv_bfloat16 g_Wh[3 * NF * NF];     // W transposed [layer][n][k], bf16 hi
__device__ __nv_bfloat16 g_Wl[3 * NF * NF];     // bf16 lo
__device__ int   g_cnt   [N_NODES];
__device__ int   g_rowptr[N_NODES + 1];
__device__ int   g_cursor[N_NODES];
__device__ float g_isq   [N_NODES];
__device__ float g_invdeg[N_NODES];
__device__ int   g_src   [N_EDGES];
__device__ float g_enorm [N_EDGES];
__device__ int   g_gstart[N_GRAPHS + 1];
__device__ int   g_is64;

// ---------------- dtype detection ----------------
__global__ void detect_dtype_kernel(const int* __restrict__ ei32) {
    if (threadIdx.x != 0 || blockIdx.x != 0) return;
    int is64 = 1;
    #pragma unroll 1
    for (int i = 0; i < 128; i++) {
        if (ei32[2 * i + 1] != 0) { is64 = 0; break; }
    }
    g_is64 = is64;
}

__device__ __forceinline__ int load_idx(const void* p, long long i, bool is64) {
    return is64 ? (int)((const long long*)p)[i] : ((const int*)p)[i];
}

// ---------------- CSR build ----------------
__global__ void zero_cnt_kernel() {
    int i = blockIdx.x * blockDim.x + threadIdx.x;
    if (i < N_NODES) g_cnt[i] = 0;
}

__global__ void count_deg_kernel(const void* __restrict__ ei) {
    bool is64 = (g_is64 != 0);
    int stride = gridDim.x * blockDim.x;
    for (int e = blockIdx.x * blockDim.x + threadIdx.x; e < N_EDGES; e += stride) {
        int dst = load_idx(ei, (long long)N_EDGES + e, is64);
        if ((unsigned)dst < (unsigned)N_NODES)
            atomicAdd(&g_cnt[dst], 1);
    }
}

__global__ void compute_isq_kernel() {
    int i = blockIdx.x * blockDim.x + threadIdx.x;
    if (i >= N_NODES) return;
    float deg = (float)(g_cnt[i] + 1);
    g_isq[i]    = rsqrtf(deg);
    g_invdeg[i] = 1.0f / deg;
}

__global__ void scan_kernel() {
    __shared__ int wsum[32];
    __shared__ int carry_s;
    int tid = threadIdx.x, lane = tid & 31, wid = tid >> 5;
    if (tid == 0) carry_s = 0;
    __syncthreads();
    for (int base = 0; base < N_NODES; base += 4096) {
        int i0 = base + tid * 4;
        int v0 = 0, v1 = 0, v2 = 0, v3 = 0;
        if (i0 + 3 < N_NODES) {
            int4 t = *(const int4*)&g_cnt[i0];
            v0 = t.x; v1 = t.y; v2 = t.z; v3 = t.w;
        } else {
            if (i0     < N_NODES) v0 = g_cnt[i0];
            if (i0 + 1 < N_NODES) v1 = g_cnt[i0 + 1];
            if (i0 + 2 < N_NODES) v2 = g_cnt[i0 + 2];
            if (i0 + 3 < N_NODES) v3 = g_cnt[i0 + 3];
        }
        int ts = v0 + v1 + v2 + v3;
        int x = ts;
        #pragma unroll
        for (int o = 1; o < 32; o <<= 1) {
            int y = __shfl_up_sync(0xffffffffu, x, o);
            if (lane >= o) x += y;
        }
        if (lane == 31) wsum[wid] = x;
        __syncthreads();
        if (wid == 0) {
            int s = wsum[lane];
            #pragma unroll
            for (int o = 1; o < 32; o <<= 1) {
                int y = __shfl_up_sync(0xffffffffu, s, o);
                if (lane >= o) s += y;
            }
            wsum[lane] = s;
        }
        __syncthreads();
        int wexcl = wid ? wsum[wid - 1] : 0;
        int excl = x - ts + wexcl + carry_s;
        int e0 = excl, e1 = e0 + v0, e2 = e1 + v1, e3 = e2 + v2;
        if (i0     < N_NODES) { g_rowptr[i0]     = e0; g_cursor[i0]     = e0; }
        if (i0 + 1 < N_NODES) { g_rowptr[i0 + 1] = e1; g_cursor[i0 + 1] = e1; }
        if (i0 + 2 < N_NODES) { g_rowptr[i0 + 2] = e2; g_cursor[i0 + 2] = e2; }
        if (i0 + 3 < N_NODES) { g_rowptr[i0 + 3] = e3; g_cursor[i0 + 3] = e3; }
        __syncthreads();
        if (tid == 1023) carry_s += wsum[31];
        __syncthreads();
    }
    if (threadIdx.x == 0) g_rowptr[N_NODES] = carry_s;
}

__global__ void scatter_edges_kernel(const void* __restrict__ ei) {
    bool is64 = (g_is64 != 0);
    int stride = gridDim.x * blockDim.x;
    for (int e = blockIdx.x * blockDim.x + threadIdx.x; e < N_EDGES; e += stride) {
        int src = load_idx(ei, e, is64);
        int dst = load_idx(ei, (long long)N_EDGES + e, is64);
        if ((unsigned)src >= (unsigned)N_NODES) continue;
        if ((unsigned)dst >= (unsigned)N_NODES) continue;
        int pos = atomicAdd(&g_cursor[dst], 1);
        if ((unsigned)pos < (unsigned)N_EDGES) {
            g_src[pos]   = src;
            g_enorm[pos] = g_isq[src] * g_isq[dst];
        }
    }
}

// ---------------- converts (bf16 hi/lo splitting) ----------------
__device__ __forceinline__ void split_bf16(float a, __nv_bfloat16& h, __nv_bfloat16& l) {
    h = __float2bfloat16(a);
    l = __float2bfloat16(a - __bfloat162float(h));
}

// W -> transposed bf16 hi/lo: g_W*[layer*NF*NF + n*NF + k] = split(W[k][n])
__global__ void convert_w_kernel(const float* __restrict__ W1,
                                 const float* __restrict__ W2,
                                 const float* __restrict__ W3) {
    int i = blockIdx.x * blockDim.x + threadIdx.x;
    if (i >= 3 * NF * NF) return;
    int layer = i / (NF * NF);
    int r = i % (NF * NF);
    int n = r / NF, k = r % NF;
    const float* W = (layer == 0) ? W1 : (layer == 1 ? W2 : W3);
    __nv_bfloat16 h, l;
    split_bf16(W[k * NF + n], h, l);
    g_Wh[i] = h;
    g_Wl[i] = l;
}

__global__ void convert_x_kernel(const float* __restrict__ x) {
    int i = blockIdx.x * blockDim.x + threadIdx.x;
    if (i * 4 >= N_NODES * NF) return;
    float4 v = ((const float4*)x)[i];
    __nv_bfloat16 h[4], l[4];
    split_bf16(v.x, h[0], l[0]);
    split_bf16(v.y, h[1], l[1]);
    split_bf16(v.z, h[2], l[2]);
    split_bf16(v.w, h[3], l[3]);
    *(__nv_bfloat162*)&g_Ah[i * 4 + 0] = __nv_bfloat162(h[0], h[1]);
    *(__nv_bfloat162*)&g_Ah[i * 4 + 2] = __nv_bfloat162(h[2], h[3]);
    *(__nv_bfloat162*)&g_Al[i * 4 + 0] = __nv_bfloat162(l[0], l[1]);
    *(__nv_bfloat162*)&g_Al[i * 4 + 2] = __nv_bfloat162(l[2], l[3]);
}

// ---------------- tensor-core GEMM ----------------
// g_xw[M x 128] = (Ah+Al) @ (Wh+Wl)  via  Ah*Wh + Ah*Wl + Al*Wh  (fp32 accum).
// Block tile 128m x 64n (grid.y=2), 8 warps in 4x2; warp tile 32m x 32n.
// smem rows padded to 48 bf16 (96 B) -> 16B-aligned uint4 stores, 2-way ldsm conflicts.
#define SPAD 48

#define LDSM4(r, addr) asm volatile( \
    "ldmatrix.sync.aligned.m8n8.x4.shared.b16 {%0,%1,%2,%3}, [%4];" \
    : "=r"((r)[0]), "=r"((r)[1]), "=r"((r)[2]), "=r"((r)[3]) : "r"(addr))

#define MMA16816(d, a, b) asm volatile( \
    "mma.sync.aligned.m16n8k16.row.col.f32.bf16.bf16.f32 " \
    "{%0,%1,%2,%3}, {%4,%5,%6,%7}, {%8,%9}, {%0,%1,%2,%3};" \
    : "+f"((d)[0]), "+f"((d)[1]), "+f"((d)[2]), "+f"((d)[3]) \
    : "r"((a)[0]), "r"((a)[1]), "r"((a)[2]), "r"((a)[3]), \
      "r"((b)[0]), "r"((b)[1]))

__global__ __launch_bounds__(256) void gemm_bf16_kernel(int layer, int M)
{
    __shared__ __align__(16) __nv_bfloat16 sAh[128 * SPAD];
    __shared__ __align__(16) __nv_bfloat16 sAl[128 * SPAD];
    __shared__ __align__(16) __nv_bfloat16 sBh[64 * SPAD];
    __shared__ __align__(16) __nv_bfloat16 sBl[64 * SPAD];

    int tid  = threadIdx.x;
    int lane = tid & 31;
    int wid  = tid >> 5;
    int m0b  = blockIdx.x * 128;
    int n0b  = blockIdx.y * 64;
    int wm   = (wid & 3) * 32;       // warp m offset within block tile
    int wn   = (wid >> 2) * 32;      // warp n offset within block tile
    const __nv_bfloat16* Wh = g_Wh + layer * NF * NF;
    const __nv_bfloat16* Wl = g_Wl + layer * NF * NF;

    unsigned sAh_u = (unsigned)__cvta_generic_to_shared(sAh);
    unsigned sAl_u = (unsigned)__cvta_generic_to_shared(sAl);
    unsigned sBh_u = (unsigned)__cvta_generic_to_shared(sBh);
    unsigned sBl_u = (unsigned)__cvta_generic_to_shared(sBl);

    // ldmatrix per-lane addressing (element offsets)
    int a_row = lane & 15;
    int a_k   = (lane >> 4) << 3;
    int b_row = ((lane >> 4) << 3) + (lane & 7);
    int b_k   = ((lane >> 3) & 1) << 3;

    float acc[2][4][4];
    #pragma unroll
    for (int mt = 0; mt < 2; mt++)
        #pragma unroll
        for (int nt = 0; nt < 4; nt++)
            #pragma unroll
            for (int c = 0; c < 4; c++) acc[mt][nt][c] = 0.f;

    #pragma unroll 1
    for (int kc = 0; kc < 4; kc++) {         // four 32-k chunks
        __syncthreads();
        // A chunk: 128 rows x 32 k (hi & lo): 512 uint4 per array, 2 iters
        #pragma unroll
        for (int it = 0; it < 2; it++) {
            int f = tid + it * 256;
            int r = f >> 2;
            int gq = (f & 3) * 8;
            int row = m0b + r;
            uint4 vh = make_uint4(0, 0, 0, 0), vl = make_uint4(0, 0, 0, 0);
            if (row < M) {
                vh = *(const uint4*)&g_Ah[row * NF + kc * 32 + gq];
                vl = *(const uint4*)&g_Al[row * NF + kc * 32 + gq];
            }
            *(uint4*)&sAh[r * SPAD + gq] = vh;
            *(uint4*)&sAl[r * SPAD + gq] = vl;
        }
        // B chunk: 64 n-rows x 32 k: 256 uint4 per array, 1 iter
        {
            int r = tid >> 2;
            int gq = (tid & 3) * 8;
            *(uint4*)&sBh[r * SPAD + gq] = *(const uint4*)&Wh[(n0b + r) * NF + kc * 32 + gq];
            *(uint4*)&sBl[r * SPAD + gq] = *(const uint4*)&Wl[(n0b + r) * NF + kc * 32 + gq];
        }
        __syncthreads();

        #pragma unroll
        for (int ks = 0; ks < 2; ks++) {     // two k16 steps per chunk
            int kk = ks * 16;
            unsigned aH[2][4], aL[2][4], bH[4][2], bL[4][2];
            #pragma unroll
            for (int mt = 0; mt < 2; mt++) {
                unsigned off = (unsigned)(((wm + mt * 16 + a_row) * SPAD + kk + a_k) * 2);
                LDSM4(aH[mt], sAh_u + off);
                LDSM4(aL[mt], sAl_u + off);
            }
            #pragma unroll
            for (int np = 0; np < 2; np++) { // each x4 covers 2 n-tiles
                unsigned off = (unsigned)(((wn + np * 16 + b_row) * SPAD + kk + b_k) * 2);
                unsigned th[4], tl[4];
                LDSM4(th, sBh_u + off);
                LDSM4(tl, sBl_u + off);
                bH[np * 2 + 0][0] = th[0]; bH[np * 2 + 0][1] = th[1];
                bH[np * 2 + 1][0] = th[2]; bH[np * 2 + 1][1] = th[3];
                bL[np * 2 + 0][0] = tl[0]; bL[np * 2 + 0][1] = tl[1];
                bL[np * 2 + 1][0] = tl[2]; bL[np * 2 + 1][1] = tl[3];
            }
            #pragma unroll
            for (int mt = 0; mt < 2; mt++)
                #pragma unroll
                for (int nt = 0; nt < 4; nt++) {
                    MMA16816(acc[mt][nt], aH[mt], bH[nt]);
                    MMA16816(acc[mt][nt], aH[mt], bL[nt]);
                    MMA16816(acc[mt][nt], aL[mt], bH[nt]);
                }
        }
    }

    // epilogue: fragment -> g_xw fp32
    #pragma unroll
    for (int mt = 0; mt < 2; mt++) {
        #pragma unroll
        for (int nt = 0; nt < 4; nt++) {
            int row = m0b + wm + mt * 16 + (lane >> 2);
            int col = n0b + wn + nt * 8 + (lane & 3) * 2;
            if (row < M)
                *(float2*)&g_xw[row * NF + col] =
                    make_float2(acc[mt][nt][0], acc[mt][nt][1]);
            if (row + 8 < M)
                *(float2*)&g_xw[(row + 8) * NF + col] =
                    make_float2(acc[mt][nt][2], acc[mt][nt][3]);
        }
    }
}

// ---------------- aggregation: warp per node, CSR gather, +self, +bias, relu ----
// mode 0: write bf16 hi/lo (feeds next GEMM).  mode 1: write fp32 g_h1 (pool).
__global__ __launch_bounds__(256) void aggregate_kernel(
    const float* __restrict__ bias, int mode)
{
    int node = (blockIdx.x * blockDim.x + threadIdx.x) >> 5;
    if (node >= N_NODES) return;
    int lane = threadIdx.x & 31;
    int beg = g_rowptr[node];
    int end = g_rowptr[node + 1];
    float ax = 0.f, ay = 0.f, az = 0.f, aw = 0.f;
    int col = lane * 4;
    for (int e = beg; e < end; e++) {
        int   s = g_src[e];
        float w = g_enorm[e];
        float4 v = *(const float4*)&g_xw[s * NF + col];
        ax += w * v.x; ay += w * v.y; az += w * v.z; aw += w * v.w;
    }
    float sd = g_invdeg[node];
    float4 vs = *(const float4*)&g_xw[node * NF + col];
    ax += sd * vs.x; ay += sd * vs.y; az += sd * vs.z; aw += sd * vs.w;
    float4 b = *(const float4*)&bias[col];
    ax = fmaxf(ax + b.x, 0.f);
    ay = fmaxf(ay + b.y, 0.f);
    az = fmaxf(az + b.z, 0.f);
    aw = fmaxf(aw + b.w, 0.f);
    if (mode == 0) {
        __nv_bfloat16 h[4], l[4];
        split_bf16(ax, h[0], l[0]);
        split_bf16(ay, h[1], l[1]);
        split_bf16(az, h[2], l[2]);
        split_bf16(aw, h[3], l[3]);
        *(__nv_bfloat162*)&g_Ah[node * NF + col + 0] = __nv_bfloat162(h[0], h[1]);
        *(__nv_bfloat162*)&g_Ah[node * NF + col + 2] = __nv_bfloat162(h[2], h[3]);
        *(__nv_bfloat162*)&g_Al[node * NF + col + 0] = __nv_bfloat162(l[0], l[1]);
        *(__nv_bfloat162*)&g_Al[node * NF + col + 2] = __nv_bfloat162(l[2], l[3]);
    } else {
        *(float4*)&g_h1[node * NF + col] = make_float4(ax, ay, az, aw);
    }
}

// ---------------- pooling + FC ----------------
__global__ void graph_bounds_kernel(const void* __restrict__ batch) {
    bool is64 = (g_is64 != 0);
    int g = blockIdx.x * blockDim.x + threadIdx.x;
    if (g > N_GRAPHS) return;
    int lo = 0, hi = N_NODES;
    while (lo < hi) {
        int mid = (lo + hi) >> 1;
        int bv = load_idx(batch, mid, is64);
        if (bv < g) lo = mid + 1; else hi = mid;
    }
    g_gstart[g] = lo;
}

__global__ void pool_fc_kernel(const float* __restrict__ Wfc,
                               const float* __restrict__ bfc,
                               float* __restrict__ out)
{
    __shared__ float red[128];
    int g = blockIdx.x;
    int t = threadIdx.x;
    int beg = g_gstart[g], end = g_gstart[g + 1];
    if (beg < 0) beg = 0;
    if (end > N_NODES) end = N_NODES;
    float s = 0.f;
    for (int n = beg; n < end; n++) s += g_h1[n * NF + t];
    float cnt = (float)(end - beg);
    float mean = (cnt > 0.f) ? (s / cnt) : 0.f;
    red[t] = mean * Wfc[t];
    __syncthreads();
    #pragma unroll
    for (int o = 64; o > 0; o >>= 1) {
        if (t < o) red[t] += red[t + o];
        __syncthreads();
    }
    if (t == 0) out[g] = red[0] + bfc[0];
}

// ---------------- launch ----------------
extern "C" void kernel_launch(void* const* d_in, const int* in_sizes, int n_in,
                              void* d_out, int out_size) {
    const float* x     = (const float*)d_in[0];
    const void*  ei    = d_in[1];
    const void*  batch = d_in[2];
    const float* W1  = (const float*)d_in[3];
    const float* b1  = (const float*)d_in[4];
    const float* W2  = (const float*)d_in[5];
    const float* b2  = (const float*)d_in[6];
    const float* W3  = (const float*)d_in[7];
    const float* b3  = (const float*)d_in[8];
    const float* Wfc = (const float*)d_in[9];
    const float* bfc = (const float*)d_in[10];
    float* out = (float*)d_out;

    // weight + input converts, CSR build
    convert_w_kernel<<<(3 * NF * NF + 255) / 256, 256>>>(W1, W2, W3);
    detect_dtype_kernel<<<1, 32>>>((const int*)ei);
    zero_cnt_kernel<<<(N_NODES + 255) / 256, 256>>>();
    count_deg_kernel<<<2048, 256>>>(ei);
    compute_isq_kernel<<<(N_NODES + 255) / 256, 256>>>();
    scan_kernel<<<1, 1024>>>();
    scatter_edges_kernel<<<2048, 256>>>(ei);
    convert_x_kernel<<<(N_NODES * NF / 4 + 255) / 256, 256>>>(x);

    dim3 gemm_grid((N_NODES + 127) / 128, 2);
    const int AGG_BLOCKS = (N_NODES * 32 + 255) / 256;

    // layer 1
    gemm_bf16_kernel<<<gemm_grid, 256>>>(0, N_NODES);
    aggregate_kernel<<<AGG_BLOCKS, 256>>>(b1, 0);
    // layer 2
    gemm_bf16_kernel<<<gemm_grid, 256>>>(1, N_NODES);
    aggregate_kernel<<<AGG_BLOCKS, 256>>>(b2, 0);
    // layer 3
    gemm_bf16_kernel<<<gemm_grid, 256>>>(2, N_NODES);
    aggregate_kernel<<<AGG_BLOCKS, 256>>>(b3, 1);

    // pool + fc
    graph_bounds_kernel<<<(N_GRAPHS + 1 + 255) / 256, 256>>>(batch);
    pool_fc_kernel<<<N_GRAPHS, 128>>>(Wfc, bfc, out);
}

// round 13
// speedup vs baseline: 1.5740x; 1.1719x over previous
#include <cuda_runtime.h>
#include <cuda_bf16.h>
#include <cuda_fp16.h>
#include <math.h>

#define N_NODES   100000
#define N_EDGES   1600000
#define NF        128
#define N_GRAPHS  1024

// ---------------- scratch (static device globals; no allocation) ----------------
__device__ __half g_xwh[N_NODES * NF];          // GEMM output (per-layer, fp16)
__device__ float g_h1 [N_NODES * NF];           // layer-3 hidden (fp32, for pool)
__device__ __nv_bfloat16 g_Ah[N_NODES * NF];    // GEMM A input, bf16 hi
__device__ __nv_bfloat16 g_Al[N_NODES * NF];    // GEMM A input, bf16 lo
__device__ __nv_bfloat16 g_Wh[3 * NF * NF];     // W transposed [layer][n][k], bf16 hi
__device__ __nv_bfloat16 g_Wl[3 * NF * NF];     // bf16 lo
__device__ int   g_cnt   [N_NODES];
__device__ int   g_rowptr[N_NODES + 1];
__device__ int   g_cursor[N_NODES];
__device__ float g_isq   [N_NODES];
__device__ float g_invdeg[N_NODES];
__device__ int   g_src   [N_EDGES];
__device__ float g_enorm [N_EDGES];
__device__ int   g_gstart[N_GRAPHS + 1];
__device__ int   g_is64;

// ---------------- dtype detection ----------------
__global__ void detect_dtype_kernel(const int* __restrict__ ei32) {
    if (threadIdx.x != 0 || blockIdx.x != 0) return;
    int is64 = 1;
    #pragma unroll 1
    for (int i = 0; i < 128; i++) {
        if (ei32[2 * i + 1] != 0) { is64 = 0; break; }
    }
    g_is64 = is64;
}

__device__ __forceinline__ int load_idx(const void* p, long long i, bool is64) {
    return is64 ? (int)((const long long*)p)[i] : ((const int*)p)[i];
}

// ---------------- CSR build ----------------
__global__ void zero_cnt_kernel() {
    int i = blockIdx.x * blockDim.x + threadIdx.x;
    if (i < N_NODES) g_cnt[i] = 0;
}

__global__ void count_deg_kernel(const void* __restrict__ ei) {
    bool is64 = (g_is64 != 0);
    int stride = gridDim.x * blockDim.x;
    for (int e = blockIdx.x * blockDim.x + threadIdx.x; e < N_EDGES; e += stride) {
        int dst = load_idx(ei, (long long)N_EDGES + e, is64);
        if ((unsigned)dst < (unsigned)N_NODES)
            atomicAdd(&g_cnt[dst], 1);
    }
}

__global__ void compute_isq_kernel() {
    int i = blockIdx.x * blockDim.x + threadIdx.x;
    if (i >= N_NODES) return;
    float deg = (float)(g_cnt[i] + 1);
    g_isq[i]    = rsqrtf(deg);
    g_invdeg[i] = 1.0f / deg;
}

__global__ void scan_kernel() {
    __shared__ int wsum[32];
    __shared__ int carry_s;
    int tid = threadIdx.x, lane = tid & 31, wid = tid >> 5;
    if (tid == 0) carry_s = 0;
    __syncthreads();
    for (int base = 0; base < N_NODES; base += 4096) {
        int i0 = base + tid * 4;
        int v0 = 0, v1 = 0, v2 = 0, v3 = 0;
        if (i0 + 3 < N_NODES) {
            int4 t = *(const int4*)&g_cnt[i0];
            v0 = t.x; v1 = t.y; v2 = t.z; v3 = t.w;
        } else {
            if (i0     < N_NODES) v0 = g_cnt[i0];
            if (i0 + 1 < N_NODES) v1 = g_cnt[i0 + 1];
            if (i0 + 2 < N_NODES) v2 = g_cnt[i0 + 2];
            if (i0 + 3 < N_NODES) v3 = g_cnt[i0 + 3];
        }
        int ts = v0 + v1 + v2 + v3;
        int x = ts;
        #pragma unroll
        for (int o = 1; o < 32; o <<= 1) {
            int y = __shfl_up_sync(0xffffffffu, x, o);
            if (lane >= o) x += y;
        }
        if (lane == 31) wsum[wid] = x;
        __syncthreads();
        if (wid == 0) {
            int s = wsum[lane];
            #pragma unroll
            for (int o = 1; o < 32; o <<= 1) {
                int y = __shfl_up_sync(0xffffffffu, s, o);
                if (lane >= o) s += y;
            }
            wsum[lane] = s;
        }
        __syncthreads();
        int wexcl = wid ? wsum[wid - 1] : 0;
        int excl = x - ts + wexcl + carry_s;
        int e0 = excl, e1 = e0 + v0, e2 = e1 + v1, e3 = e2 + v2;
        if (i0     < N_NODES) { g_rowptr[i0]     = e0; g_cursor[i0]     = e0; }
        if (i0 + 1 < N_NODES) { g_rowptr[i0 + 1] = e1; g_cursor[i0 + 1] = e1; }
        if (i0 + 2 < N_NODES) { g_rowptr[i0 + 2] = e2; g_cursor[i0 + 2] = e2; }
        if (i0 + 3 < N_NODES) { g_rowptr[i0 + 3] = e3; g_cursor[i0 + 3] = e3; }
        __syncthreads();
        if (tid == 1023) carry_s += wsum[31];
        __syncthreads();
    }
    if (threadIdx.x == 0) g_rowptr[N_NODES] = carry_s;
}

__global__ void scatter_edges_kernel(const void* __restrict__ ei) {
    bool is64 = (g_is64 != 0);
    int stride = gridDim.x * blockDim.x;
    for (int e = blockIdx.x * blockDim.x + threadIdx.x; e < N_EDGES; e += stride) {
        int src = load_idx(ei, e, is64);
        int dst = load_idx(ei, (long long)N_EDGES + e, is64);
        if ((unsigned)src >= (unsigned)N_NODES) continue;
        if ((unsigned)dst >= (unsigned)N_NODES) continue;
        int pos = atomicAdd(&g_cursor[dst], 1);
        if ((unsigned)pos < (unsigned)N_EDGES) {
            g_src[pos]   = src;
            g_enorm[pos] = g_isq[src] * g_isq[dst];
        }
    }
}

// ---------------- converts (bf16 hi/lo splitting) ----------------
__device__ __forceinline__ void split_bf16(float a, __nv_bfloat16& h, __nv_bfloat16& l) {
    h = __float2bfloat16(a);
    l = __float2bfloat16(a - __bfloat162float(h));
}

__global__ void convert_w_kernel(const float* __restrict__ W1,
                                 const float* __restrict__ W2,
                                 const float* __restrict__ W3) {
    int i = blockIdx.x * blockDim.x + threadIdx.x;
    if (i >= 3 * NF * NF) return;
    int layer = i / (NF * NF);
    int r = i % (NF * NF);
    int n = r / NF, k = r % NF;
    const float* W = (layer == 0) ? W1 : (layer == 1 ? W2 : W3);
    __nv_bfloat16 h, l;
    split_bf16(W[k * NF + n], h, l);
    g_Wh[i] = h;
    g_Wl[i] = l;
}

__global__ void convert_x_kernel(const float* __restrict__ x) {
    int i = blockIdx.x * blockDim.x + threadIdx.x;
    if (i * 4 >= N_NODES * NF) return;
    float4 v = ((const float4*)x)[i];
    __nv_bfloat16 h[4], l[4];
    split_bf16(v.x, h[0], l[0]);
    split_bf16(v.y, h[1], l[1]);
    split_bf16(v.z, h[2], l[2]);
    split_bf16(v.w, h[3], l[3]);
    *(__nv_bfloat162*)&g_Ah[i * 4 + 0] = __nv_bfloat162(h[0], h[1]);
    *(__nv_bfloat162*)&g_Ah[i * 4 + 2] = __nv_bfloat162(h[2], h[3]);
    *(__nv_bfloat162*)&g_Al[i * 4 + 0] = __nv_bfloat162(l[0], l[1]);
    *(__nv_bfloat162*)&g_Al[i * 4 + 2] = __nv_bfloat162(l[2], l[3]);
}

// ---------------- tensor-core GEMM ----------------
// g_xwh[M x 128] = (Ah+Al) @ (Wh+Wl)  via  Ah*Wh + Ah*Wl + Al*Wh  (fp32 accum,
// fp16 output). Block tile 128m x 64n (grid.y=2), 8 warps 4x2; warp 32m x 32n.
// SPAD=40 (80 B rows): ldmatrix 8-row phases hit banks {0,20,8,28,16,4,24,12}
// -> conflict-free; 16 B alignment preserved.
#define SPAD 40

#define LDSM4(r, addr) asm volatile( \
    "ldmatrix.sync.aligned.m8n8.x4.shared.b16 {%0,%1,%2,%3}, [%4];" \
    : "=r"((r)[0]), "=r"((r)[1]), "=r"((r)[2]), "=r"((r)[3]) : "r"(addr))

#define MMA16816(d, a, b) asm volatile( \
    "mma.sync.aligned.m16n8k16.row.col.f32.bf16.bf16.f32 " \
    "{%0,%1,%2,%3}, {%4,%5,%6,%7}, {%8,%9}, {%0,%1,%2,%3};" \
    : "+f"((d)[0]), "+f"((d)[1]), "+f"((d)[2]), "+f"((d)[3]) \
    : "r"((a)[0]), "r"((a)[1]), "r"((a)[2]), "r"((a)[3]), \
      "r"((b)[0]), "r"((b)[1]))

__global__ __launch_bounds__(256) void gemm_bf16_kernel(int layer, int M)
{
    __shared__ __align__(16) __nv_bfloat16 sAh[128 * SPAD];
    __shared__ __align__(16) __nv_bfloat16 sAl[128 * SPAD];
    __shared__ __align__(16) __nv_bfloat16 sBh[64 * SPAD];
    __shared__ __align__(16) __nv_bfloat16 sBl[64 * SPAD];

    int tid  = threadIdx.x;
    int lane = tid & 31;
    int wid  = tid >> 5;
    int m0b  = blockIdx.x * 128;
    int n0b  = blockIdx.y * 64;
    int wm   = (wid & 3) * 32;
    int wn   = (wid >> 2) * 32;
    const __nv_bfloat16* Wh = g_Wh + layer * NF * NF;
    const __nv_bfloat16* Wl = g_Wl + layer * NF * NF;

    unsigned sAh_u = (unsigned)__cvta_generic_to_shared(sAh);
    unsigned sAl_u = (unsigned)__cvta_generic_to_shared(sAl);
    unsigned sBh_u = (unsigned)__cvta_generic_to_shared(sBh);
    unsigned sBl_u = (unsigned)__cvta_generic_to_shared(sBl);

    int a_row = lane & 15;
    int a_k   = (lane >> 4) << 3;
    int b_row = ((lane >> 4) << 3) + (lane & 7);
    int b_k   = ((lane >> 3) & 1) << 3;

    float acc[2][4][4];
    #pragma unroll
    for (int mt = 0; mt < 2; mt++)
        #pragma unroll
        for (int nt = 0; nt < 4; nt++)
            #pragma unroll
            for (int c = 0; c < 4; c++) acc[mt][nt][c] = 0.f;

    #pragma unroll 1
    for (int kc = 0; kc < 4; kc++) {
        __syncthreads();
        #pragma unroll
        for (int it = 0; it < 2; it++) {
            int f = tid + it * 256;
            int r = f >> 2;
            int gq = (f & 3) * 8;
            int row = m0b + r;
            uint4 vh = make_uint4(0, 0, 0, 0), vl = make_uint4(0, 0, 0, 0);
            if (row < M) {
                vh = *(const uint4*)&g_Ah[row * NF + kc * 32 + gq];
                vl = *(const uint4*)&g_Al[row * NF + kc * 32 + gq];
            }
            *(uint4*)&sAh[r * SPAD + gq] = vh;
            *(uint4*)&sAl[r * SPAD + gq] = vl;
        }
        {
            int r = tid >> 2;
            int gq = (tid & 3) * 8;
            *(uint4*)&sBh[r * SPAD + gq] = *(const uint4*)&Wh[(n0b + r) * NF + kc * 32 + gq];
            *(uint4*)&sBl[r * SPAD + gq] = *(const uint4*)&Wl[(n0b + r) * NF + kc * 32 + gq];
        }
        __syncthreads();

        #pragma unroll
        for (int ks = 0; ks < 2; ks++) {
            int kk = ks * 16;
            unsigned aH[2][4], aL[2][4], bH[4][2], bL[4][2];
            #pragma unroll
            for (int mt = 0; mt < 2; mt++) {
                unsigned off = (unsigned)(((wm + mt * 16 + a_row) * SPAD + kk + a_k) * 2);
                LDSM4(aH[mt], sAh_u + off);
                LDSM4(aL[mt], sAl_u + off);
            }
            #pragma unroll
            for (int np = 0; np < 2; np++) {
                unsigned off = (unsigned)(((wn + np * 16 + b_row) * SPAD + kk + b_k) * 2);
                unsigned th[4], tl[4];
                LDSM4(th, sBh_u + off);
                LDSM4(tl, sBl_u + off);
                bH[np * 2 + 0][0] = th[0]; bH[np * 2 + 0][1] = th[1];
                bH[np * 2 + 1][0] = th[2]; bH[np * 2 + 1][1] = th[3];
                bL[np * 2 + 0][0] = tl[0]; bL[np * 2 + 0][1] = tl[1];
                bL[np * 2 + 1][0] = tl[2]; bL[np * 2 + 1][1] = tl[3];
            }
            #pragma unroll
            for (int mt = 0; mt < 2; mt++)
                #pragma unroll
                for (int nt = 0; nt < 4; nt++) {
                    MMA16816(acc[mt][nt], aH[mt], bH[nt]);
                    MMA16816(acc[mt][nt], aH[mt], bL[nt]);
                    MMA16816(acc[mt][nt], aL[mt], bH[nt]);
                }
        }
    }

    // epilogue: fragment -> g_xwh fp16
    #pragma unroll
    for (int mt = 0; mt < 2; mt++) {
        #pragma unroll
        for (int nt = 0; nt < 4; nt++) {
            int row = m0b + wm + mt * 16 + (lane >> 2);
            int col = n0b + wn + nt * 8 + (lane & 3) * 2;
            if (row < M)
                *(__half2*)&g_xwh[row * NF + col] =
                    __floats2half2_rn(acc[mt][nt][0], acc[mt][nt][1]);
            if (row + 8 < M)
                *(__half2*)&g_xwh[(row + 8) * NF + col] =
                    __floats2half2_rn(acc[mt][nt][2], acc[mt][nt][3]);
        }
    }
}

// ---------------- aggregation: warp per node, CSR gather (fp16), fp32 accum ----
// mode 0: write bf16 hi/lo (feeds next GEMM).  mode 1: write fp32 g_h1 (pool).
__global__ __launch_bounds__(256) void aggregate_kernel(
    const float* __restrict__ bias, int mode)
{
    int node = (blockIdx.x * blockDim.x + threadIdx.x) >> 5;
    if (node >= N_NODES) return;
    int lane = threadIdx.x & 31;
    int beg = g_rowptr[node];
    int end = g_rowptr[node + 1];
    float ax = 0.f, ay = 0.f, az = 0.f, aw = 0.f;
    int col = lane * 4;
    for (int e = beg; e < end; e++) {
        int   s = g_src[e];
        float w = g_enorm[e];
        uint2 u = *(const uint2*)&g_xwh[s * NF + col];
        float2 f0 = __half22float2(*(__half2*)&u.x);
        float2 f1 = __half22float2(*(__half2*)&u.y);
        ax += w * f0.x; ay += w * f0.y; az += w * f1.x; aw += w * f1.y;
    }
    float sd = g_invdeg[node];
    {
        uint2 u = *(const uint2*)&g_xwh[node * NF + col];
        float2 f0 = __half22float2(*(__half2*)&u.x);
        float2 f1 = __half22float2(*(__half2*)&u.y);
        ax += sd * f0.x; ay += sd * f0.y; az += sd * f1.x; aw += sd * f1.y;
    }
    float4 b = *(const float4*)&bias[col];
    ax = fmaxf(ax + b.x, 0.f);
    ay = fmaxf(ay + b.y, 0.f);
    az = fmaxf(az + b.z, 0.f);
    aw = fmaxf(aw + b.w, 0.f);
    if (mode == 0) {
        __nv_bfloat16 h[4], l[4];
        split_bf16(ax, h[0], l[0]);
        split_bf16(ay, h[1], l[1]);
        split_bf16(az, h[2], l[2]);
        split_bf16(aw, h[3], l[3]);
        *(__nv_bfloat162*)&g_Ah[node * NF + col + 0] = __nv_bfloat162(h[0], h[1]);
        *(__nv_bfloat162*)&g_Ah[node * NF + col + 2] = __nv_bfloat162(h[2], h[3]);
        *(__nv_bfloat162*)&g_Al[node * NF + col + 0] = __nv_bfloat162(l[0], l[1]);
        *(__nv_bfloat162*)&g_Al[node * NF + col + 2] = __nv_bfloat162(l[2], l[3]);
    } else {
        *(float4*)&g_h1[node * NF + col] = make_float4(ax, ay, az, aw);
    }
}

// ---------------- pooling + FC ----------------
__global__ void graph_bounds_kernel(const void* __restrict__ batch) {
    bool is64 = (g_is64 != 0);
    int g = blockIdx.x * blockDim.x + threadIdx.x;
    if (g > N_GRAPHS) return;
    int lo = 0, hi = N_NODES;
    while (lo < hi) {
        int mid = (lo + hi) >> 1;
        int bv = load_idx(batch, mid, is64);
        if (bv < g) lo = mid + 1; else hi = mid;
    }
    g_gstart[g] = lo;
}

__global__ void pool_fc_kernel(const float* __restrict__ Wfc,
                               const float* __restrict__ bfc,
                               float* __restrict__ out)
{
    __shared__ float red[128];
    int g = blockIdx.x;
    int t = threadIdx.x;
    int beg = g_gstart[g], end = g_gstart[g + 1];
    if (beg < 0) beg = 0;
    if (end > N_NODES) end = N_NODES;
    float s = 0.f;
    for (int n = beg; n < end; n++) s += g_h1[n * NF + t];
    float cnt = (float)(end - beg);
    float mean = (cnt > 0.f) ? (s / cnt) : 0.f;
    red[t] = mean * Wfc[t];
    __syncthreads();
    #pragma unroll
    for (int o = 64; o > 0; o >>= 1) {
        if (t < o) red[t] += red[t + o];
        __syncthreads();
    }
    if (t == 0) out[g] = red[0] + bfc[0];
}

// ---------------- launch ----------------
extern "C" void kernel_launch(void* const* d_in, const int* in_sizes, int n_in,
                              void* d_out, int out_size) {
    const float* x     = (const float*)d_in[0];
    const void*  ei    = d_in[1];
    const void*  batch = d_in[2];
    const float* W1  = (const float*)d_in[3];
    const float* b1  = (const float*)d_in[4];
    const float* W2  = (const float*)d_in[5];
    const float* b2  = (const float*)d_in[6];
    const float* W3  = (const float*)d_in[7];
    const float* b3  = (const float*)d_in[8];
    const float* Wfc = (const float*)d_in[9];
    const float* bfc = (const float*)d_in[10];
    float* out = (float*)d_out;

    convert_w_kernel<<<(3 * NF * NF + 255) / 256, 256>>>(W1, W2, W3);
    detect_dtype_kernel<<<1, 32>>>((const int*)ei);
    zero_cnt_kernel<<<(N_NODES + 255) / 256, 256>>>();
    count_deg_kernel<<<2048, 256>>>(ei);
    compute_isq_kernel<<<(N_NODES + 255) / 256, 256>>>();
    scan_kernel<<<1, 1024>>>();
    scatter_edges_kernel<<<2048, 256>>>(ei);
    convert_x_kernel<<<(N_NODES * NF / 4 + 255) / 256, 256>>>(x);

    dim3 gemm_grid((N_NODES + 127) / 128, 2);
    const int AGG_BLOCKS = (N_NODES * 32 + 255) / 256;

    // layer 1
    gemm_bf16_kernel<<<gemm_grid, 256>>>(0, N_NODES);
    aggregate_kernel<<<AGG_BLOCKS, 256>>>(b1, 0);
    // layer 2
    gemm_bf16_kernel<<<gemm_grid, 256>>>(1, N_NODES);
    aggregate_kernel<<<AGG_BLOCKS, 256>>>(b2, 0);
    // layer 3
    gemm_bf16_kernel<<<gemm_grid, 256>>>(2, N_NODES);
    aggregate_kernel<<<AGG_BLOCKS, 256>>>(b3, 1);

    // pool + fc
    graph_bounds_kernel<<<(N_GRAPHS + 1 + 255) / 256, 256>>>(batch);
    pool_fc_kernel<<<N_GRAPHS, 128>>>(Wfc, bfc, out);
}

// round 14
// speedup vs baseline: 1.7044x; 1.0829x over previous
#include <cuda_runtime.h>
#include <cuda_bf16.h>
#include <cuda_fp16.h>
#include <math.h>

#define N_NODES   100000
#define N_EDGES   1600000
#define NF        128
#define N_GRAPHS  1024

// ---------------- scratch (static device globals; no allocation) ----------------
__device__ __half g_xwh[N_NODES * NF];          // GEMM output (per-layer, fp16)
__device__ float g_h1 [N_NODES * NF];           // layer-3 hidden (fp32, for pool)
__device__ __nv_bfloat16 g_Ah[N_NODES * NF];    // GEMM A input, bf16 hi
__device__ __nv_bfloat16 g_Al[N_NODES * NF];    // GEMM A input, bf16 lo
__device__ __nv_bfloat16 g_Wh[3 * NF * NF];     // W transposed [layer][n][k], bf16 hi
__device__ __nv_bfloat16 g_Wl[3 * NF * NF];     // bf16 lo
__device__ int   g_cnt   [N_NODES];
__device__ int   g_rowptr[N_NODES + 1];
__device__ int   g_cursor[N_NODES];
__device__ float g_isq   [N_NODES];
__device__ float g_invdeg[N_NODES];
__device__ int2  g_edge  [N_EDGES];             // {src, norm-as-int} packed
__device__ int   g_gstart[N_GRAPHS + 1];
__device__ int   g_is64;

// ---------------- dtype detection ----------------
__global__ void detect_dtype_kernel(const int* __restrict__ ei32) {
    if (threadIdx.x != 0 || blockIdx.x != 0) return;
    int is64 = 1;
    #pragma unroll 1
    for (int i = 0; i < 128; i++) {
        if (ei32[2 * i + 1] != 0) { is64 = 0; break; }
    }
    g_is64 = is64;
}

__device__ __forceinline__ int load_idx(const void* p, long long i, bool is64) {
    return is64 ? (int)((const long long*)p)[i] : ((const int*)p)[i];
}

// ---------------- CSR build ----------------
__global__ void zero_cnt_kernel() {
    int i = blockIdx.x * blockDim.x + threadIdx.x;
    if (i < N_NODES) g_cnt[i] = 0;
}

__global__ void count_deg_kernel(const void* __restrict__ ei) {
    bool is64 = (g_is64 != 0);
    int stride = gridDim.x * blockDim.x;
    for (int e = blockIdx.x * blockDim.x + threadIdx.x; e < N_EDGES; e += stride) {
        int dst = load_idx(ei, (long long)N_EDGES + e, is64);
        if ((unsigned)dst < (unsigned)N_NODES)
            atomicAdd(&g_cnt[dst], 1);
    }
}

__global__ void compute_isq_kernel() {
    int i = blockIdx.x * blockDim.x + threadIdx.x;
    if (i >= N_NODES) return;
    float deg = (float)(g_cnt[i] + 1);
    g_isq[i]    = rsqrtf(deg);
    g_invdeg[i] = 1.0f / deg;
}

__global__ void scan_kernel() {
    __shared__ int wsum[32];
    __shared__ int carry_s;
    int tid = threadIdx.x, lane = tid & 31, wid = tid >> 5;
    if (tid == 0) carry_s = 0;
    __syncthreads();
    for (int base = 0; base < N_NODES; base += 4096) {
        int i0 = base + tid * 4;
        int v0 = 0, v1 = 0, v2 = 0, v3 = 0;
        if (i0 + 3 < N_NODES) {
            int4 t = *(const int4*)&g_cnt[i0];
            v0 = t.x; v1 = t.y; v2 = t.z; v3 = t.w;
        } else {
            if (i0     < N_NODES) v0 = g_cnt[i0];
            if (i0 + 1 < N_NODES) v1 = g_cnt[i0 + 1];
            if (i0 + 2 < N_NODES) v2 = g_cnt[i0 + 2];
            if (i0 + 3 < N_NODES) v3 = g_cnt[i0 + 3];
        }
        int ts = v0 + v1 + v2 + v3;
        int x = ts;
        #pragma unroll
        for (int o = 1; o < 32; o <<= 1) {
            int y = __shfl_up_sync(0xffffffffu, x, o);
            if (lane >= o) x += y;
        }
        if (lane == 31) wsum[wid] = x;
        __syncthreads();
        if (wid == 0) {
            int s = wsum[lane];
            #pragma unroll
            for (int o = 1; o < 32; o <<= 1) {
                int y = __shfl_up_sync(0xffffffffu, s, o);
                if (lane >= o) s += y;
            }
            wsum[lane] = s;
        }
        __syncthreads();
        int wexcl = wid ? wsum[wid - 1] : 0;
        int excl = x - ts + wexcl + carry_s;
        int e0 = excl, e1 = e0 + v0, e2 = e1 + v1, e3 = e2 + v2;
        if (i0     < N_NODES) { g_rowptr[i0]     = e0; g_cursor[i0]     = e0; }
        if (i0 + 1 < N_NODES) { g_rowptr[i0 + 1] = e1; g_cursor[i0 + 1] = e1; }
        if (i0 + 2 < N_NODES) { g_rowptr[i0 + 2] = e2; g_cursor[i0 + 2] = e2; }
        if (i0 + 3 < N_NODES) { g_rowptr[i0 + 3] = e3; g_cursor[i0 + 3] = e3; }
        __syncthreads();
        if (tid == 1023) carry_s += wsum[31];
        __syncthreads();
    }
    if (threadIdx.x == 0) g_rowptr[N_NODES] = carry_s;
}

__global__ void scatter_edges_kernel(const void* __restrict__ ei) {
    bool is64 = (g_is64 != 0);
    int stride = gridDim.x * blockDim.x;
    for (int e = blockIdx.x * blockDim.x + threadIdx.x; e < N_EDGES; e += stride) {
        int src = load_idx(ei, e, is64);
        int dst = load_idx(ei, (long long)N_EDGES + e, is64);
        if ((unsigned)src >= (unsigned)N_NODES) continue;
        if ((unsigned)dst >= (unsigned)N_NODES) continue;
        int pos = atomicAdd(&g_cursor[dst], 1);
        if ((unsigned)pos < (unsigned)N_EDGES) {
            float nrm = g_isq[src] * g_isq[dst];
            g_edge[pos] = make_int2(src, __float_as_int(nrm));
        }
    }
}

// ---------------- converts (bf16 hi/lo splitting) ----------------
__device__ __forceinline__ void split_bf16(float a, __nv_bfloat16& h, __nv_bfloat16& l) {
    h = __float2bfloat16(a);
    l = __float2bfloat16(a - __bfloat162float(h));
}

__global__ void convert_w_kernel(const float* __restrict__ W1,
                                 const float* __restrict__ W2,
                                 const float* __restrict__ W3) {
    int i = blockIdx.x * blockDim.x + threadIdx.x;
    if (i >= 3 * NF * NF) return;
    int layer = i / (NF * NF);
    int r = i % (NF * NF);
    int n = r / NF, k = r % NF;
    const float* W = (layer == 0) ? W1 : (layer == 1 ? W2 : W3);
    __nv_bfloat16 h, l;
    split_bf16(W[k * NF + n], h, l);
    g_Wh[i] = h;
    g_Wl[i] = l;
}

__global__ void convert_x_kernel(const float* __restrict__ x) {
    int i = blockIdx.x * blockDim.x + threadIdx.x;
    if (i * 4 >= N_NODES * NF) return;
    float4 v = ((const float4*)x)[i];
    __nv_bfloat16 h[4], l[4];
    split_bf16(v.x, h[0], l[0]);
    split_bf16(v.y, h[1], l[1]);
    split_bf16(v.z, h[2], l[2]);
    split_bf16(v.w, h[3], l[3]);
    *(__nv_bfloat162*)&g_Ah[i * 4 + 0] = __nv_bfloat162(h[0], h[1]);
    *(__nv_bfloat162*)&g_Ah[i * 4 + 2] = __nv_bfloat162(h[2], h[3]);
    *(__nv_bfloat162*)&g_Al[i * 4 + 0] = __nv_bfloat162(l[0], l[1]);
    *(__nv_bfloat162*)&g_Al[i * 4 + 2] = __nv_bfloat162(l[2], l[3]);
}

// ---------------- tensor-core GEMM ----------------
// g_xwh[M x 128] = (Ah+Al) @ (Wh+Wl)  via  Ah*Wh + Ah*Wl + Al*Wh  (fp32 accum,
// fp16 output). Block tile 128m x 64n (grid.y=2), 8 warps 4x2; warp 32m x 32n.
// SPAD=40 (80 B rows): ldmatrix phases conflict-free, 16 B alignment preserved.
#define SPAD 40

#define LDSM4(r, addr) asm volatile( \
    "ldmatrix.sync.aligned.m8n8.x4.shared.b16 {%0,%1,%2,%3}, [%4];" \
    : "=r"((r)[0]), "=r"((r)[1]), "=r"((r)[2]), "=r"((r)[3]) : "r"(addr))

#define MMA16816(d, a, b) asm volatile( \
    "mma.sync.aligned.m16n8k16.row.col.f32.bf16.bf16.f32 " \
    "{%0,%1,%2,%3}, {%4,%5,%6,%7}, {%8,%9}, {%0,%1,%2,%3};" \
    : "+f"((d)[0]), "+f"((d)[1]), "+f"((d)[2]), "+f"((d)[3]) \
    : "r"((a)[0]), "r"((a)[1]), "r"((a)[2]), "r"((a)[3]), \
      "r"((b)[0]), "r"((b)[1]))

__global__ __launch_bounds__(256) void gemm_bf16_kernel(int layer, int M)
{
    __shared__ __align__(16) __nv_bfloat16 sAh[128 * SPAD];
    __shared__ __align__(16) __nv_bfloat16 sAl[128 * SPAD];
    __shared__ __align__(16) __nv_bfloat16 sBh[64 * SPAD];
    __shared__ __align__(16) __nv_bfloat16 sBl[64 * SPAD];

    int tid  = threadIdx.x;
    int lane = tid & 31;
    int wid  = tid >> 5;
    int m0b  = blockIdx.x * 128;
    int n0b  = blockIdx.y * 64;
    int wm   = (wid & 3) * 32;
    int wn   = (wid >> 2) * 32;
    const __nv_bfloat16* Wh = g_Wh + layer * NF * NF;
    const __nv_bfloat16* Wl = g_Wl + layer * NF * NF;

    unsigned sAh_u = (unsigned)__cvta_generic_to_shared(sAh);
    unsigned sAl_u = (unsigned)__cvta_generic_to_shared(sAl);
    unsigned sBh_u = (unsigned)__cvta_generic_to_shared(sBh);
    unsigned sBl_u = (unsigned)__cvta_generic_to_shared(sBl);

    int a_row = lane & 15;
    int a_k   = (lane >> 4) << 3;
    int b_row = ((lane >> 4) << 3) + (lane & 7);
    int b_k   = ((lane >> 3) & 1) << 3;

    float acc[2][4][4];
    #pragma unroll
    for (int mt = 0; mt < 2; mt++)
        #pragma unroll
        for (int nt = 0; nt < 4; nt++)
            #pragma unroll
            for (int c = 0; c < 4; c++) acc[mt][nt][c] = 0.f;

    #pragma unroll 1
    for (int kc = 0; kc < 4; kc++) {
        __syncthreads();
        #pragma unroll
        for (int it = 0; it < 2; it++) {
            int f = tid + it * 256;
            int r = f >> 2;
            int gq = (f & 3) * 8;
            int row = m0b + r;
            uint4 vh = make_uint4(0, 0, 0, 0), vl = make_uint4(0, 0, 0, 0);
            if (row < M) {
                vh = *(const uint4*)&g_Ah[row * NF + kc * 32 + gq];
                vl = *(const uint4*)&g_Al[row * NF + kc * 32 + gq];
            }
            *(uint4*)&sAh[r * SPAD + gq] = vh;
            *(uint4*)&sAl[r * SPAD + gq] = vl;
        }
        {
            int r = tid >> 2;
            int gq = (tid & 3) * 8;
            *(uint4*)&sBh[r * SPAD + gq] = *(const uint4*)&Wh[(n0b + r) * NF + kc * 32 + gq];
            *(uint4*)&sBl[r * SPAD + gq] = *(const uint4*)&Wl[(n0b + r) * NF + kc * 32 + gq];
        }
        __syncthreads();

        #pragma unroll
        for (int ks = 0; ks < 2; ks++) {
            int kk = ks * 16;
            unsigned aH[2][4], aL[2][4], bH[4][2], bL[4][2];
            #pragma unroll
            for (int mt = 0; mt < 2; mt++) {
                unsigned off = (unsigned)(((wm + mt * 16 + a_row) * SPAD + kk + a_k) * 2);
                LDSM4(aH[mt], sAh_u + off);
                LDSM4(aL[mt], sAl_u + off);
            }
            #pragma unroll
            for (int np = 0; np < 2; np++) {
                unsigned off = (unsigned)(((wn + np * 16 + b_row) * SPAD + kk + b_k) * 2);
                unsigned th[4], tl[4];
                LDSM4(th, sBh_u + off);
                LDSM4(tl, sBl_u + off);
                bH[np * 2 + 0][0] = th[0]; bH[np * 2 + 0][1] = th[1];
                bH[np * 2 + 1][0] = th[2]; bH[np * 2 + 1][1] = th[3];
                bL[np * 2 + 0][0] = tl[0]; bL[np * 2 + 0][1] = tl[1];
                bL[np * 2 + 1][0] = tl[2]; bL[np * 2 + 1][1] = tl[3];
            }
            #pragma unroll
            for (int mt = 0; mt < 2; mt++)
                #pragma unroll
                for (int nt = 0; nt < 4; nt++) {
                    MMA16816(acc[mt][nt], aH[mt], bH[nt]);
                    MMA16816(acc[mt][nt], aH[mt], bL[nt]);
                    MMA16816(acc[mt][nt], aL[mt], bH[nt]);
                }
        }
    }

    #pragma unroll
    for (int mt = 0; mt < 2; mt++) {
        #pragma unroll
        for (int nt = 0; nt < 4; nt++) {
            int row = m0b + wm + mt * 16 + (lane >> 2);
            int col = n0b + wn + nt * 8 + (lane & 3) * 2;
            if (row < M)
                *(__half2*)&g_xwh[row * NF + col] =
                    __floats2half2_rn(acc[mt][nt][0], acc[mt][nt][1]);
            if (row + 8 < M)
                *(__half2*)&g_xwh[(row + 8) * NF + col] =
                    __floats2half2_rn(acc[mt][nt][2], acc[mt][nt][3]);
        }
    }
}

// ---------------- aggregation: warp per node, CSR gather (fp16), fp32 accum ----
// mode 0: write bf16 hi/lo (feeds next GEMM).  mode 1: write fp32 g_h1 (pool).
__global__ __launch_bounds__(256) void aggregate_kernel(
    const float* __restrict__ bias, int mode)
{
    int node = (blockIdx.x * blockDim.x + threadIdx.x) >> 5;
    if (node >= N_NODES) return;
    int lane = threadIdx.x & 31;
    int beg = g_rowptr[node];
    int end = g_rowptr[node + 1];
    float ax = 0.f, ay = 0.f, az = 0.f, aw = 0.f;
    int col = lane * 4;
    int e = beg;
    for (; e + 1 < end; e += 2) {                 // 2 gather rows in flight
        int2 ed0 = g_edge[e];
        int2 ed1 = g_edge[e + 1];
        uint2 u0 = *(const uint2*)&g_xwh[ed0.x * NF + col];
        uint2 u1 = *(const uint2*)&g_xwh[ed1.x * NF + col];
        float w0 = __int_as_float(ed0.y);
        float w1 = __int_as_float(ed1.y);
        float2 a0 = __half22float2(*(__half2*)&u0.x);
        float2 b0 = __half22float2(*(__half2*)&u0.y);
        float2 a1 = __half22float2(*(__half2*)&u1.x);
        float2 b1 = __half22float2(*(__half2*)&u1.y);
        ax += w0 * a0.x + w1 * a1.x;
        ay += w0 * a0.y + w1 * a1.y;
        az += w0 * b0.x + w1 * b1.x;
        aw += w0 * b0.y + w1 * b1.y;
    }
    if (e < end) {
        int2 ed = g_edge[e];
        uint2 u = *(const uint2*)&g_xwh[ed.x * NF + col];
        float w = __int_as_float(ed.y);
        float2 a0 = __half22float2(*(__half2*)&u.x);
        float2 b0 = __half22float2(*(__half2*)&u.y);
        ax += w * a0.x; ay += w * a0.y; az += w * b0.x; aw += w * b0.y;
    }
    float sd = g_invdeg[node];
    {
        uint2 u = *(const uint2*)&g_xwh[node * NF + col];
        float2 a0 = __half22float2(*(__half2*)&u.x);
        float2 b0 = __half22float2(*(__half2*)&u.y);
        ax += sd * a0.x; ay += sd * a0.y; az += sd * b0.x; aw += sd * b0.y;
    }
    float4 b = *(const float4*)&bias[col];
    ax = fmaxf(ax + b.x, 0.f);
    ay = fmaxf(ay + b.y, 0.f);
    az = fmaxf(az + b.z, 0.f);
    aw = fmaxf(aw + b.w, 0.f);
    if (mode == 0) {
        __nv_bfloat16 h[4], l[4];
        split_bf16(ax, h[0], l[0]);
        split_bf16(ay, h[1], l[1]);
        split_bf16(az, h[2], l[2]);
        split_bf16(aw, h[3], l[3]);
        *(__nv_bfloat162*)&g_Ah[node * NF + col + 0] = __nv_bfloat162(h[0], h[1]);
        *(__nv_bfloat162*)&g_Ah[node * NF + col + 2] = __nv_bfloat162(h[2], h[3]);
        *(__nv_bfloat162*)&g_Al[node * NF + col + 0] = __nv_bfloat162(l[0], l[1]);
        *(__nv_bfloat162*)&g_Al[node * NF + col + 2] = __nv_bfloat162(l[2], l[3]);
    } else {
        *(float4*)&g_h1[node * NF + col] = make_float4(ax, ay, az, aw);
    }
}

// ---------------- pooling + FC ----------------
__global__ void graph_bounds_kernel(const void* __restrict__ batch) {
    bool is64 = (g_is64 != 0);
    int g = blockIdx.x * blockDim.x + threadIdx.x;
    if (g > N_GRAPHS) return;
    int lo = 0, hi = N_NODES;
    while (lo < hi) {
        int mid = (lo + hi) >> 1;
        int bv = load_idx(batch, mid, is64);
        if (bv < g) lo = mid + 1; else hi = mid;
    }
    g_gstart[g] = lo;
}

__global__ void pool_fc_kernel(const float* __restrict__ Wfc,
                               const float* __restrict__ bfc,
                               float* __restrict__ out)
{
    __shared__ float red[128];
    int g = blockIdx.x;
    int t = threadIdx.x;
    int beg = g_gstart[g], end = g_gstart[g + 1];
    if (beg < 0) beg = 0;
    if (end > N_NODES) end = N_NODES;
    float s = 0.f;
    for (int n = beg; n < end; n++) s += g_h1[n * NF + t];
    float cnt = (float)(end - beg);
    float mean = (cnt > 0.f) ? (s / cnt) : 0.f;
    red[t] = mean * Wfc[t];
    __syncthreads();
    #pragma unroll
    for (int o = 64; o > 0; o >>= 1) {
        if (t < o) red[t] += red[t + o];
        __syncthreads();
    }
    if (t == 0) out[g] = red[0] + bfc[0];
}

// ---------------- launch ----------------
extern "C" void kernel_launch(void* const* d_in, const int* in_sizes, int n_in,
                              void* d_out, int out_size) {
    const float* x     = (const float*)d_in[0];
    const void*  ei    = d_in[1];
    const void*  batch = d_in[2];
    const float* W1  = (const float*)d_in[3];
    const float* b1  = (const float*)d_in[4];
    const float* W2  = (const float*)d_in[5];
    const float* b2  = (const float*)d_in[6];
    const float* W3  = (const float*)d_in[7];
    const float* b3  = (const float*)d_in[8];
    const float* Wfc = (const float*)d_in[9];
    const float* bfc = (const float*)d_in[10];
    float* out = (float*)d_out;

    // Fork a side stream for the CSR build; it is independent of the
    // convert + layer-1 GEMM chain. Created fresh per call, never destroyed
    // (kernel_launch runs only for correctness + capture; replays reuse the
    // captured graph, so there is no growth).
    cudaStream_t s2;
    cudaEvent_t evFork, evJoin;
    cudaStreamCreateWithFlags(&s2, cudaStreamNonBlocking);
    cudaEventCreateWithFlags(&evFork, cudaEventDisableTiming);
    cudaEventCreateWithFlags(&evJoin, cudaEventDisableTiming);

    cudaEventRecord(evFork, 0);
    cudaStreamWaitEvent(s2, evFork, 0);

    // branch B (s2): CSR build + graph bounds
    detect_dtype_kernel<<<1, 32, 0, s2>>>((const int*)ei);
    zero_cnt_kernel<<<(N_NODES + 255) / 256, 256, 0, s2>>>();
    count_deg_kernel<<<2048, 256, 0, s2>>>(ei);
    compute_isq_kernel<<<(N_NODES + 255) / 256, 256, 0, s2>>>();
    scan_kernel<<<1, 1024, 0, s2>>>();
    scatter_edges_kernel<<<2048, 256, 0, s2>>>(ei);
    graph_bounds_kernel<<<(N_GRAPHS + 1 + 255) / 256, 256, 0, s2>>>(batch);
    cudaEventRecord(evJoin, s2);

    // branch A (default stream): converts + layer-1 GEMM
    convert_w_kernel<<<(3 * NF * NF + 255) / 256, 256>>>(W1, W2, W3);
    convert_x_kernel<<<(N_NODES * NF / 4 + 255) / 256, 256>>>(x);

    dim3 gemm_grid((N_NODES + 127) / 128, 2);
    const int AGG_BLOCKS = (N_NODES * 32 + 255) / 256;

    gemm_bf16_kernel<<<gemm_grid, 256>>>(0, N_NODES);

    // join: aggregation needs the CSR
    cudaStreamWaitEvent(0, evJoin, 0);

    aggregate_kernel<<<AGG_BLOCKS, 256>>>(b1, 0);
    // layer 2
    gemm_bf16_kernel<<<gemm_grid, 256>>>(1, N_NODES);
    aggregate_kernel<<<AGG_BLOCKS, 256>>>(b2, 0);
    // layer 3
    gemm_bf16_kernel<<<gemm_grid, 256>>>(2, N_NODES);
    aggregate_kernel<<<AGG_BLOCKS, 256>>>(b3, 1);

    // pool + fc
    pool_fc_kernel<<<N_GRAPHS, 128>>>(Wfc, bfc, out);
}

// round 15
// speedup vs baseline: 1.9049x; 1.1177x over previous
#include <cuda_runtime.h>
#include <cuda_bf16.h>
#include <cuda_fp16.h>
#include <math.h>

#define N_NODES   100000
#define N_EDGES   1600000
#define NF        128
#define N_GRAPHS  1024

// ---------------- scratch (static device globals; no allocation) ----------------
__device__ __half g_xwh[N_NODES * NF];   // GEMM output (per-layer, fp16)
__device__ __half g_A  [N_NODES * NF];   // GEMM A input (fp16)
__device__ float  g_h1 [N_NODES * NF];   // layer-3 hidden (fp32, for pool)
__device__ __half g_Wh [3 * NF * NF];    // W transposed [layer][n][k], fp16 hi
__device__ __half g_Wl [3 * NF * NF];    // fp16 residual
__device__ int   g_cnt   [N_NODES];
__device__ int   g_rowptr[N_NODES + 1];
__device__ int   g_cursor[N_NODES];
__device__ float g_isq   [N_NODES];
__device__ float g_invdeg[N_NODES];
__device__ int2  g_edge  [N_EDGES];      // {src, norm-as-int} packed
__device__ int   g_gstart[N_GRAPHS + 1];
__device__ int   g_is64;

// ---------------- dtype detection ----------------
__global__ void detect_dtype_kernel(const int* __restrict__ ei32) {
    if (threadIdx.x != 0 || blockIdx.x != 0) return;
    int is64 = 1;
    #pragma unroll 1
    for (int i = 0; i < 128; i++) {
        if (ei32[2 * i + 1] != 0) { is64 = 0; break; }
    }
    g_is64 = is64;
}

__device__ __forceinline__ int load_idx(const void* p, long long i, bool is64) {
    return is64 ? (int)((const long long*)p)[i] : ((const int*)p)[i];
}

// ---------------- CSR build ----------------
__global__ void zero_cnt_kernel() {
    int i = blockIdx.x * blockDim.x + threadIdx.x;
    if (i < N_NODES) g_cnt[i] = 0;
}

__global__ void count_deg_kernel(const void* __restrict__ ei) {
    bool is64 = (g_is64 != 0);
    int stride = gridDim.x * blockDim.x;
    for (int e = blockIdx.x * blockDim.x + threadIdx.x; e < N_EDGES; e += stride) {
        int dst = load_idx(ei, (long long)N_EDGES + e, is64);
        if ((unsigned)dst < (unsigned)N_NODES)
            atomicAdd(&g_cnt[dst], 1);
    }
}

__global__ void compute_isq_kernel() {
    int i = blockIdx.x * blockDim.x + threadIdx.x;
    if (i >= N_NODES) return;
    float deg = (float)(g_cnt[i] + 1);
    g_isq[i]    = rsqrtf(deg);
    g_invdeg[i] = 1.0f / deg;
}

__global__ void scan_kernel() {
    __shared__ int wsum[32];
    __shared__ int carry_s;
    int tid = threadIdx.x, lane = tid & 31, wid = tid >> 5;
    if (tid == 0) carry_s = 0;
    __syncthreads();
    for (int base = 0; base < N_NODES; base += 4096) {
        int i0 = base + tid * 4;
        int v0 = 0, v1 = 0, v2 = 0, v3 = 0;
        if (i0 + 3 < N_NODES) {
            int4 t = *(const int4*)&g_cnt[i0];
            v0 = t.x; v1 = t.y; v2 = t.z; v3 = t.w;
        } else {
            if (i0     < N_NODES) v0 = g_cnt[i0];
            if (i0 + 1 < N_NODES) v1 = g_cnt[i0 + 1];
            if (i0 + 2 < N_NODES) v2 = g_cnt[i0 + 2];
            if (i0 + 3 < N_NODES) v3 = g_cnt[i0 + 3];
        }
        int ts = v0 + v1 + v2 + v3;
        int x = ts;
        #pragma unroll
        for (int o = 1; o < 32; o <<= 1) {
            int y = __shfl_up_sync(0xffffffffu, x, o);
            if (lane >= o) x += y;
        }
        if (lane == 31) wsum[wid] = x;
        __syncthreads();
        if (wid == 0) {
            int s = wsum[lane];
            #pragma unroll
            for (int o = 1; o < 32; o <<= 1) {
                int y = __shfl_up_sync(0xffffffffu, s, o);
                if (lane >= o) s += y;
            }
            wsum[lane] = s;
        }
        __syncthreads();
        int wexcl = wid ? wsum[wid - 1] : 0;
        int excl = x - ts + wexcl + carry_s;
        int e0 = excl, e1 = e0 + v0, e2 = e1 + v1, e3 = e2 + v2;
        if (i0     < N_NODES) { g_rowptr[i0]     = e0; g_cursor[i0]     = e0; }
        if (i0 + 1 < N_NODES) { g_rowptr[i0 + 1] = e1; g_cursor[i0 + 1] = e1; }
        if (i0 + 2 < N_NODES) { g_rowptr[i0 + 2] = e2; g_cursor[i0 + 2] = e2; }
        if (i0 + 3 < N_NODES) { g_rowptr[i0 + 3] = e3; g_cursor[i0 + 3] = e3; }
        __syncthreads();
        if (tid == 1023) carry_s += wsum[31];
        __syncthreads();
    }
    if (threadIdx.x == 0) g_rowptr[N_NODES] = carry_s;
}

__global__ void scatter_edges_kernel(const void* __restrict__ ei) {
    bool is64 = (g_is64 != 0);
    int stride = gridDim.x * blockDim.x;
    for (int e = blockIdx.x * blockDim.x + threadIdx.x; e < N_EDGES; e += stride) {
        int src = load_idx(ei, e, is64);
        int dst = load_idx(ei, (long long)N_EDGES + e, is64);
        if ((unsigned)src >= (unsigned)N_NODES) continue;
        if ((unsigned)dst >= (unsigned)N_NODES) continue;
        int pos = atomicAdd(&g_cursor[dst], 1);
        if ((unsigned)pos < (unsigned)N_EDGES) {
            float nrm = g_isq[src] * g_isq[dst];
            g_edge[pos] = make_int2(src, __float_as_int(nrm));
        }
    }
}

// ---------------- converts ----------------
// W -> transposed fp16 hi/residual: g_W*[layer*NF*NF + n*NF + k] from W[k][n]
__global__ void convert_w_kernel(const float* __restrict__ W1,
                                 const float* __restrict__ W2,
                                 const float* __restrict__ W3) {
    int i = blockIdx.x * blockDim.x + threadIdx.x;
    if (i >= 3 * NF * NF) return;
    int layer = i / (NF * NF);
    int r = i % (NF * NF);
    int n = r / NF, k = r % NF;
    const float* W = (layer == 0) ? W1 : (layer == 1 ? W2 : W3);
    float w = W[k * NF + n];
    __half h = __float2half_rn(w);
    __half l = __float2half_rn(w - __half2float(h));
    g_Wh[i] = h;
    g_Wl[i] = l;
}

__global__ void convert_x_kernel(const float* __restrict__ x) {
    int i = blockIdx.x * blockDim.x + threadIdx.x;
    if (i * 4 >= N_NODES * NF) return;
    float4 v = ((const float4*)x)[i];
    __half2 p0 = __floats2half2_rn(v.x, v.y);
    __half2 p1 = __floats2half2_rn(v.z, v.w);
    *(__half2*)&g_A[i * 4 + 0] = p0;
    *(__half2*)&g_A[i * 4 + 2] = p1;
}

// ---------------- tensor-core GEMM ----------------
// g_xwh[M x 128] = A @ (Wh+Wl)   (A fp16, W fp16-split, fp32 accum, fp16 out).
// Block tile 128m x 64n (grid.y=2), 8 warps 4x2; warp 32m x 32n.
// SPAD=40 (80 B rows): ldmatrix phases conflict-free, 16 B alignment preserved.
#define SPAD 40

#define LDSM4(r, addr) asm volatile( \
    "ldmatrix.sync.aligned.m8n8.x4.shared.b16 {%0,%1,%2,%3}, [%4];" \
    : "=r"((r)[0]), "=r"((r)[1]), "=r"((r)[2]), "=r"((r)[3]) : "r"(addr))

#define MMA16816F16(d, a, b) asm volatile( \
    "mma.sync.aligned.m16n8k16.row.col.f32.f16.f16.f32 " \
    "{%0,%1,%2,%3}, {%4,%5,%6,%7}, {%8,%9}, {%0,%1,%2,%3};" \
    : "+f"((d)[0]), "+f"((d)[1]), "+f"((d)[2]), "+f"((d)[3]) \
    : "r"((a)[0]), "r"((a)[1]), "r"((a)[2]), "r"((a)[3]), \
      "r"((b)[0]), "r"((b)[1]))

__global__ __launch_bounds__(256) void gemm_f16_kernel(int layer, int M)
{
    __shared__ __align__(16) __half sA [128 * SPAD];
    __shared__ __align__(16) __half sBh[64 * SPAD];
    __shared__ __align__(16) __half sBl[64 * SPAD];

    int tid  = threadIdx.x;
    int lane = tid & 31;
    int wid  = tid >> 5;
    int m0b  = blockIdx.x * 128;
    int n0b  = blockIdx.y * 64;
    int wm   = (wid & 3) * 32;
    int wn   = (wid >> 2) * 32;
    const __half* Wh = g_Wh + layer * NF * NF;
    const __half* Wl = g_Wl + layer * NF * NF;

    unsigned sA_u  = (unsigned)__cvta_generic_to_shared(sA);
    unsigned sBh_u = (unsigned)__cvta_generic_to_shared(sBh);
    unsigned sBl_u = (unsigned)__cvta_generic_to_shared(sBl);

    int a_row = lane & 15;
    int a_k   = (lane >> 4) << 3;
    int b_row = ((lane >> 4) << 3) + (lane & 7);
    int b_k   = ((lane >> 3) & 1) << 3;

    float acc[2][4][4];
    #pragma unroll
    for (int mt = 0; mt < 2; mt++)
        #pragma unroll
        for (int nt = 0; nt < 4; nt++)
            #pragma unroll
            for (int c = 0; c < 4; c++) acc[mt][nt][c] = 0.f;

    #pragma unroll 1
    for (int kc = 0; kc < 4; kc++) {
        __syncthreads();
        // A chunk: 128 rows x 32 k: 512 uint4, 2 iters
        #pragma unroll
        for (int it = 0; it < 2; it++) {
            int f = tid + it * 256;
            int r = f >> 2;
            int gq = (f & 3) * 8;
            int row = m0b + r;
            uint4 va = make_uint4(0, 0, 0, 0);
            if (row < M) va = *(const uint4*)&g_A[row * NF + kc * 32 + gq];
            *(uint4*)&sA[r * SPAD + gq] = va;
        }
        // B chunk: 64 n-rows x 32 k: 256 uint4 per array
        {
            int r = tid >> 2;
            int gq = (tid & 3) * 8;
            *(uint4*)&sBh[r * SPAD + gq] = *(const uint4*)&Wh[(n0b + r) * NF + kc * 32 + gq];
            *(uint4*)&sBl[r * SPAD + gq] = *(const uint4*)&Wl[(n0b + r) * NF + kc * 32 + gq];
        }
        __syncthreads();

        #pragma unroll
        for (int ks = 0; ks < 2; ks++) {
            int kk = ks * 16;
            unsigned aF[2][4], bH[4][2], bL[4][2];
            #pragma unroll
            for (int mt = 0; mt < 2; mt++) {
                unsigned off = (unsigned)(((wm + mt * 16 + a_row) * SPAD + kk + a_k) * 2);
                LDSM4(aF[mt], sA_u + off);
            }
            #pragma unroll
            for (int np = 0; np < 2; np++) {
                unsigned off = (unsigned)(((wn + np * 16 + b_row) * SPAD + kk + b_k) * 2);
                unsigned th[4], tl[4];
                LDSM4(th, sBh_u + off);
                LDSM4(tl, sBl_u + off);
                bH[np * 2 + 0][0] = th[0]; bH[np * 2 + 0][1] = th[1];
                bH[np * 2 + 1][0] = th[2]; bH[np * 2 + 1][1] = th[3];
                bL[np * 2 + 0][0] = tl[0]; bL[np * 2 + 0][1] = tl[1];
                bL[np * 2 + 1][0] = tl[2]; bL[np * 2 + 1][1] = tl[3];
            }
            #pragma unroll
            for (int mt = 0; mt < 2; mt++)
                #pragma unroll
                for (int nt = 0; nt < 4; nt++) {
                    MMA16816F16(acc[mt][nt], aF[mt], bH[nt]);
                    MMA16816F16(acc[mt][nt], aF[mt], bL[nt]);
                }
        }
    }

    #pragma unroll
    for (int mt = 0; mt < 2; mt++) {
        #pragma unroll
        for (int nt = 0; nt < 4; nt++) {
            int row = m0b + wm + mt * 16 + (lane >> 2);
            int col = n0b + wn + nt * 8 + (lane & 3) * 2;
            if (row < M)
                *(__half2*)&g_xwh[row * NF + col] =
                    __floats2half2_rn(acc[mt][nt][0], acc[mt][nt][1]);
            if (row + 8 < M)
                *(__half2*)&g_xwh[(row + 8) * NF + col] =
                    __floats2half2_rn(acc[mt][nt][2], acc[mt][nt][3]);
        }
    }
}

// ---------------- aggregation: warp per node, CSR gather (fp16), fp32 accum ----
// mode 0: write fp16 g_A (feeds next GEMM).  mode 1: write fp32 g_h1 (pool).
__global__ __launch_bounds__(256) void aggregate_kernel(
    const float* __restrict__ bias, int mode)
{
    int node = (blockIdx.x * blockDim.x + threadIdx.x) >> 5;
    if (node >= N_NODES) return;
    int lane = threadIdx.x & 31;
    int beg = g_rowptr[node];
    int end = g_rowptr[node + 1];
    float ax = 0.f, ay = 0.f, az = 0.f, aw = 0.f;
    int col = lane * 4;
    int e = beg;
    for (; e + 1 < end; e += 2) {                 // 2 gather rows in flight
        int2 ed0 = g_edge[e];
        int2 ed1 = g_edge[e + 1];
        uint2 u0 = *(const uint2*)&g_xwh[ed0.x * NF + col];
        uint2 u1 = *(const uint2*)&g_xwh[ed1.x * NF + col];
        float w0 = __int_as_float(ed0.y);
        float w1 = __int_as_float(ed1.y);
        float2 a0 = __half22float2(*(__half2*)&u0.x);
        float2 b0 = __half22float2(*(__half2*)&u0.y);
        float2 a1 = __half22float2(*(__half2*)&u1.x);
        float2 b1 = __half22float2(*(__half2*)&u1.y);
        ax += w0 * a0.x + w1 * a1.x;
        ay += w0 * a0.y + w1 * a1.y;
        az += w0 * b0.x + w1 * b1.x;
        aw += w0 * b0.y + w1 * b1.y;
    }
    if (e < end) {
        int2 ed = g_edge[e];
        uint2 u = *(const uint2*)&g_xwh[ed.x * NF + col];
        float w = __int_as_float(ed.y);
        float2 a0 = __half22float2(*(__half2*)&u.x);
        float2 b0 = __half22float2(*(__half2*)&u.y);
        ax += w * a0.x; ay += w * a0.y; az += w * b0.x; aw += w * b0.y;
    }
    float sd = g_invdeg[node];
    {
        uint2 u = *(const uint2*)&g_xwh[node * NF + col];
        float2 a0 = __half22float2(*(__half2*)&u.x);
        float2 b0 = __half22float2(*(__half2*)&u.y);
        ax += sd * a0.x; ay += sd * a0.y; az += sd * b0.x; aw += sd * b0.y;
    }
    float4 b = *(const float4*)&bias[col];
    ax = fmaxf(ax + b.x, 0.f);
    ay = fmaxf(ay + b.y, 0.f);
    az = fmaxf(az + b.z, 0.f);
    aw = fmaxf(aw + b.w, 0.f);
    if (mode == 0) {
        __half2 p0 = __floats2half2_rn(ax, ay);
        __half2 p1 = __floats2half2_rn(az, aw);
        *(__half2*)&g_A[node * NF + col + 0] = p0;
        *(__half2*)&g_A[node * NF + col + 2] = p1;
    } else {
        *(float4*)&g_h1[node * NF + col] = make_float4(ax, ay, az, aw);
    }
}

// ---------------- pooling + FC ----------------
__global__ void graph_bounds_kernel(const void* __restrict__ batch) {
    bool is64 = (g_is64 != 0);
    int g = blockIdx.x * blockDim.x + threadIdx.x;
    if (g > N_GRAPHS) return;
    int lo = 0, hi = N_NODES;
    while (lo < hi) {
        int mid = (lo + hi) >> 1;
        int bv = load_idx(batch, mid, is64);
        if (bv < g) lo = mid + 1; else hi = mid;
    }
    g_gstart[g] = lo;
}

__global__ void pool_fc_kernel(const float* __restrict__ Wfc,
                               const float* __restrict__ bfc,
                               float* __restrict__ out)
{
    __shared__ float red[128];
    int g = blockIdx.x;
    int t = threadIdx.x;
    int beg = g_gstart[g], end = g_gstart[g + 1];
    if (beg < 0) beg = 0;
    if (end > N_NODES) end = N_NODES;
    float s = 0.f;
    for (int n = beg; n < end; n++) s += g_h1[n * NF + t];
    float cnt = (float)(end - beg);
    float mean = (cnt > 0.f) ? (s / cnt) : 0.f;
    red[t] = mean * Wfc[t];
    __syncthreads();
    #pragma unroll
    for (int o = 64; o > 0; o >>= 1) {
        if (t < o) red[t] += red[t + o];
        __syncthreads();
    }
    if (t == 0) out[g] = red[0] + bfc[0];
}

// ---------------- launch ----------------
extern "C" void kernel_launch(void* const* d_in, const int* in_sizes, int n_in,
                              void* d_out, int out_size) {
    const float* x     = (const float*)d_in[0];
    const void*  ei    = d_in[1];
    const void*  batch = d_in[2];
    const float* W1  = (const float*)d_in[3];
    const float* b1  = (const float*)d_in[4];
    const float* W2  = (const float*)d_in[5];
    const float* b2  = (const float*)d_in[6];
    const float* W3  = (const float*)d_in[7];
    const float* b3  = (const float*)d_in[8];
    const float* Wfc = (const float*)d_in[9];
    const float* bfc = (const float*)d_in[10];
    float* out = (float*)d_out;

    // Fork a side stream for the CSR build (independent of converts + GEMM-1).
    cudaStream_t s2;
    cudaEvent_t evFork, evJoin;
    cudaStreamCreateWithFlags(&s2, cudaStreamNonBlocking);
    cudaEventCreateWithFlags(&evFork, cudaEventDisableTiming);
    cudaEventCreateWithFlags(&evJoin, cudaEventDisableTiming);

    cudaEventRecord(evFork, 0);
    cudaStreamWaitEvent(s2, evFork, 0);

    // branch B (s2): CSR build + graph bounds
    detect_dtype_kernel<<<1, 32, 0, s2>>>((const int*)ei);
    zero_cnt_kernel<<<(N_NODES + 255) / 256, 256, 0, s2>>>();
    count_deg_kernel<<<2048, 256, 0, s2>>>(ei);
    compute_isq_kernel<<<(N_NODES + 255) / 256, 256, 0, s2>>>();
    scan_kernel<<<1, 1024, 0, s2>>>();
    scatter_edges_kernel<<<2048, 256, 0, s2>>>(ei);
    graph_bounds_kernel<<<(N_GRAPHS + 1 + 255) / 256, 256, 0, s2>>>(batch);
    cudaEventRecord(evJoin, s2);

    // branch A (default stream): converts + layer-1 GEMM
    convert_w_kernel<<<(3 * NF * NF + 255) / 256, 256>>>(W1, W2, W3);
    convert_x_kernel<<<(N_NODES * NF / 4 + 255) / 256, 256>>>(x);

    dim3 gemm_grid((N_NODES + 127) / 128, 2);
    const int AGG_BLOCKS = (N_NODES * 32 + 255) / 256;

    gemm_f16_kernel<<<gemm_grid, 256>>>(0, N_NODES);

    // join: aggregation needs the CSR
    cudaStreamWaitEvent(0, evJoin, 0);

    aggregate_kernel<<<AGG_BLOCKS, 256>>>(b1, 0);
    // layer 2
    gemm_f16_kernel<<<gemm_grid, 256>>>(1, N_NODES);
    aggregate_kernel<<<AGG_BLOCKS, 256>>>(b2, 0);
    // layer 3
    gemm_f16_kernel<<<gemm_grid, 256>>>(2, N_NODES);
    aggregate_kernel<<<AGG_BLOCKS, 256>>>(b3, 1);

    // pool + fc
    pool_fc_kernel<<<N_GRAPHS, 128>>>(Wfc, bfc, out);
}

// round 16
// speedup vs baseline: 1.9418x; 1.0193x over previous
#include <cuda_runtime.h>
#include <cuda_bf16.h>
#include <cuda_fp16.h>
#include <math.h>

#define N_NODES   100000
#define N_EDGES   1600000
#define NF        128
#define N_GRAPHS  1024

// ---------------- scratch (static device globals; no allocation) ----------------
__device__ __half g_xwh[N_NODES * NF];   // GEMM output (per-layer, fp16)
__device__ __half g_A  [N_NODES * NF];   // GEMM A input / final hidden (fp16)
__device__ __half g_Wh [3 * NF * NF];    // W transposed [layer][n][k], fp16 hi
__device__ __half g_Wl [3 * NF * NF];    // fp16 residual
__device__ int   g_cnt   [N_NODES];
__device__ int   g_rowptr[N_NODES + 1];
__device__ int   g_cursor[N_NODES];
__device__ float g_isq   [N_NODES];
__device__ float g_invdeg[N_NODES];
__device__ int2  g_edge  [N_EDGES];      // {src, norm-as-int} packed
__device__ int   g_gstart[N_GRAPHS + 1];
__device__ int   g_is64;

// ---------------- init: dtype detect + zero counts (fused) ----------------
__global__ void init_kernel(const int* __restrict__ ei32) {
    int i = blockIdx.x * blockDim.x + threadIdx.x;
    if (i < N_NODES) g_cnt[i] = 0;
    if (i == 0) {
        int is64 = 1;
        #pragma unroll 1
        for (int k = 0; k < 128; k++) {
            if (ei32[2 * k + 1] != 0) { is64 = 0; break; }
        }
        g_is64 = is64;
    }
}

__device__ __forceinline__ int load_idx(const void* p, long long i, bool is64) {
    return is64 ? (int)((const long long*)p)[i] : ((const int*)p)[i];
}

// ---------------- CSR build ----------------
// two edges per thread, vectorized dst loads
__global__ void count_deg_kernel(const void* __restrict__ ei) {
    bool is64 = (g_is64 != 0);
    int stride = gridDim.x * blockDim.x;
    const int half = N_EDGES / 2;            // N_EDGES even
    if (is64) {
        const ulonglong2* dst2 = (const ulonglong2*)((const long long*)ei + N_EDGES);
        for (int e = blockIdx.x * blockDim.x + threadIdx.x; e < half; e += stride) {
            ulonglong2 d = dst2[e];
            int d0 = (int)d.x, d1 = (int)d.y;
            if ((unsigned)d0 < (unsigned)N_NODES) atomicAdd(&g_cnt[d0], 1);
            if ((unsigned)d1 < (unsigned)N_NODES) atomicAdd(&g_cnt[d1], 1);
        }
    } else {
        const int2* dst2 = (const int2*)((const int*)ei + N_EDGES);
        for (int e = blockIdx.x * blockDim.x + threadIdx.x; e < half; e += stride) {
            int2 d = dst2[e];
            if ((unsigned)d.x < (unsigned)N_NODES) atomicAdd(&g_cnt[d.x], 1);
            if ((unsigned)d.y < (unsigned)N_NODES) atomicAdd(&g_cnt[d.y], 1);
        }
    }
}

__global__ void compute_isq_kernel() {
    int i = blockIdx.x * blockDim.x + threadIdx.x;
    if (i >= N_NODES) return;
    float deg = (float)(g_cnt[i] + 1);
    g_isq[i]    = rsqrtf(deg);
    g_invdeg[i] = 1.0f / deg;
}

__global__ void scan_kernel() {
    __shared__ int wsum[32];
    __shared__ int carry_s;
    int tid = threadIdx.x, lane = tid & 31, wid = tid >> 5;
    if (tid == 0) carry_s = 0;
    __syncthreads();
    for (int base = 0; base < N_NODES; base += 4096) {
        int i0 = base + tid * 4;
        int v0 = 0, v1 = 0, v2 = 0, v3 = 0;
        if (i0 + 3 < N_NODES) {
            int4 t = *(const int4*)&g_cnt[i0];
            v0 = t.x; v1 = t.y; v2 = t.z; v3 = t.w;
        } else {
            if (i0     < N_NODES) v0 = g_cnt[i0];
            if (i0 + 1 < N_NODES) v1 = g_cnt[i0 + 1];
            if (i0 + 2 < N_NODES) v2 = g_cnt[i0 + 2];
            if (i0 + 3 < N_NODES) v3 = g_cnt[i0 + 3];
        }
        int ts = v0 + v1 + v2 + v3;
        int x = ts;
        #pragma unroll
        for (int o = 1; o < 32; o <<= 1) {
            int y = __shfl_up_sync(0xffffffffu, x, o);
            if (lane >= o) x += y;
        }
        if (lane == 31) wsum[wid] = x;
        __syncthreads();
        if (wid == 0) {
            int s = wsum[lane];
            #pragma unroll
            for (int o = 1; o < 32; o <<= 1) {
                int y = __shfl_up_sync(0xffffffffu, s, o);
                if (lane >= o) s += y;
            }
            wsum[lane] = s;
        }
        __syncthreads();
        int wexcl = wid ? wsum[wid - 1] : 0;
        int excl = x - ts + wexcl + carry_s;
        int e0 = excl, e1 = e0 + v0, e2 = e1 + v1, e3 = e2 + v2;
        if (i0     < N_NODES) { g_rowptr[i0]     = e0; g_cursor[i0]     = e0; }
        if (i0 + 1 < N_NODES) { g_rowptr[i0 + 1] = e1; g_cursor[i0 + 1] = e1; }
        if (i0 + 2 < N_NODES) { g_rowptr[i0 + 2] = e2; g_cursor[i0 + 2] = e2; }
        if (i0 + 3 < N_NODES) { g_rowptr[i0 + 3] = e3; g_cursor[i0 + 3] = e3; }
        __syncthreads();
        if (tid == 1023) carry_s += wsum[31];
        __syncthreads();
    }
    if (threadIdx.x == 0) g_rowptr[N_NODES] = carry_s;
}

__global__ void scatter_edges_kernel(const void* __restrict__ ei) {
    bool is64 = (g_is64 != 0);
    int stride = gridDim.x * blockDim.x;
    for (int e = blockIdx.x * blockDim.x + threadIdx.x; e < N_EDGES; e += stride) {
        int src = load_idx(ei, e, is64);
        int dst = load_idx(ei, (long long)N_EDGES + e, is64);
        if ((unsigned)src >= (unsigned)N_NODES) continue;
        if ((unsigned)dst >= (unsigned)N_NODES) continue;
        int pos = atomicAdd(&g_cursor[dst], 1);
        if ((unsigned)pos < (unsigned)N_EDGES) {
            float nrm = g_isq[src] * g_isq[dst];
            g_edge[pos] = make_int2(src, __float_as_int(nrm));
        }
    }
}

// ---------------- converts ----------------
__global__ void convert_w_kernel(const float* __restrict__ W1,
                                 const float* __restrict__ W2,
                                 const float* __restrict__ W3) {
    int i = blockIdx.x * blockDim.x + threadIdx.x;
    if (i >= 3 * NF * NF) return;
    int layer = i / (NF * NF);
    int r = i % (NF * NF);
    int n = r / NF, k = r % NF;
    const float* W = (layer == 0) ? W1 : (layer == 1 ? W2 : W3);
    float w = W[k * NF + n];
    __half h = __float2half_rn(w);
    __half l = __float2half_rn(w - __half2float(h));
    g_Wh[i] = h;
    g_Wl[i] = l;
}

__global__ void convert_x_kernel(const float* __restrict__ x) {
    int i = blockIdx.x * blockDim.x + threadIdx.x;
    if (i * 4 >= N_NODES * NF) return;
    float4 v = ((const float4*)x)[i];
    *(__half2*)&g_A[i * 4 + 0] = __floats2half2_rn(v.x, v.y);
    *(__half2*)&g_A[i * 4 + 2] = __floats2half2_rn(v.z, v.w);
}

// ---------------- tensor-core GEMM ----------------
// g_xwh[M x 128] = A @ (Wh+Wl)   (A fp16, W fp16-split, fp32 accum, fp16 out).
// Block tile 128m x 64n (grid.y=2), 8 warps 4x2; warp 32m x 32n.
// SPAD=40 (80 B rows): ldmatrix phases conflict-free, 16 B alignment preserved.
#define SPAD 40

#define LDSM4(r, addr) asm volatile( \
    "ldmatrix.sync.aligned.m8n8.x4.shared.b16 {%0,%1,%2,%3}, [%4];" \
    : "=r"((r)[0]), "=r"((r)[1]), "=r"((r)[2]), "=r"((r)[3]) : "r"(addr))

#define MMA16816F16(d, a, b) asm volatile( \
    "mma.sync.aligned.m16n8k16.row.col.f32.f16.f16.f32 " \
    "{%0,%1,%2,%3}, {%4,%5,%6,%7}, {%8,%9}, {%0,%1,%2,%3};" \
    : "+f"((d)[0]), "+f"((d)[1]), "+f"((d)[2]), "+f"((d)[3]) \
    : "r"((a)[0]), "r"((a)[1]), "r"((a)[2]), "r"((a)[3]), \
      "r"((b)[0]), "r"((b)[1]))

__global__ __launch_bounds__(256) void gemm_f16_kernel(int layer, int M)
{
    __shared__ __align__(16) __half sA [128 * SPAD];
    __shared__ __align__(16) __half sBh[64 * SPAD];
    __shared__ __align__(16) __half sBl[64 * SPAD];

    int tid  = threadIdx.x;
    int lane = tid & 31;
    int wid  = tid >> 5;
    int m0b  = blockIdx.x * 128;
    int n0b  = blockIdx.y * 64;
    int wm   = (wid & 3) * 32;
    int wn   = (wid >> 2) * 32;
    const __half* Wh = g_Wh + layer * NF * NF;
    const __half* Wl = g_Wl + layer * NF * NF;

    unsigned sA_u  = (unsigned)__cvta_generic_to_shared(sA);
    unsigned sBh_u = (unsigned)__cvta_generic_to_shared(sBh);
    unsigned sBl_u = (unsigned)__cvta_generic_to_shared(sBl);

    int a_row = lane & 15;
    int a_k   = (lane >> 4) << 3;
    int b_row = ((lane >> 4) << 3) + (lane & 7);
    int b_k   = ((lane >> 3) & 1) << 3;

    float acc[2][4][4];
    #pragma unroll
    for (int mt = 0; mt < 2; mt++)
        #pragma unroll
        for (int nt = 0; nt < 4; nt++)
            #pragma unroll
            for (int c = 0; c < 4; c++) acc[mt][nt][c] = 0.f;

    #pragma unroll 1
    for (int kc = 0; kc < 4; kc++) {
        __syncthreads();
        #pragma unroll
        for (int it = 0; it < 2; it++) {
            int f = tid + it * 256;
            int r = f >> 2;
            int gq = (f & 3) * 8;
            int row = m0b + r;
            uint4 va = make_uint4(0, 0, 0, 0);
            if (row < M) va = *(const uint4*)&g_A[row * NF + kc * 32 + gq];
            *(uint4*)&sA[r * SPAD + gq] = va;
        }
        {
            int r = tid >> 2;
            int gq = (tid & 3) * 8;
            *(uint4*)&sBh[r * SPAD + gq] = *(const uint4*)&Wh[(n0b + r) * NF + kc * 32 + gq];
            *(uint4*)&sBl[r * SPAD + gq] = *(const uint4*)&Wl[(n0b + r) * NF + kc * 32 + gq];
        }
        __syncthreads();

        #pragma unroll
        for (int ks = 0; ks < 2; ks++) {
            int kk = ks * 16;
            unsigned aF[2][4], bH[4][2], bL[4][2];
            #pragma unroll
            for (int mt = 0; mt < 2; mt++) {
                unsigned off = (unsigned)(((wm + mt * 16 + a_row) * SPAD + kk + a_k) * 2);
                LDSM4(aF[mt], sA_u + off);
            }
            #pragma unroll
            for (int np = 0; np < 2; np++) {
                unsigned off = (unsigned)(((wn + np * 16 + b_row) * SPAD + kk + b_k) * 2);
                unsigned th[4], tl[4];
                LDSM4(th, sBh_u + off);
                LDSM4(tl, sBl_u + off);
                bH[np * 2 + 0][0] = th[0]; bH[np * 2 + 0][1] = th[1];
                bH[np * 2 + 1][0] = th[2]; bH[np * 2 + 1][1] = th[3];
                bL[np * 2 + 0][0] = tl[0]; bL[np * 2 + 0][1] = tl[1];
                bL[np * 2 + 1][0] = tl[2]; bL[np * 2 + 1][1] = tl[3];
            }
            #pragma unroll
            for (int mt = 0; mt < 2; mt++)
                #pragma unroll
                for (int nt = 0; nt < 4; nt++) {
                    MMA16816F16(acc[mt][nt], aF[mt], bH[nt]);
                    MMA16816F16(acc[mt][nt], aF[mt], bL[nt]);
                }
        }
    }

    #pragma unroll
    for (int mt = 0; mt < 2; mt++) {
        #pragma unroll
        for (int nt = 0; nt < 4; nt++) {
            int row = m0b + wm + mt * 16 + (lane >> 2);
            int col = n0b + wn + nt * 8 + (lane & 3) * 2;
            if (row < M)
                *(__half2*)&g_xwh[row * NF + col] =
                    __floats2half2_rn(acc[mt][nt][0], acc[mt][nt][1]);
            if (row + 8 < M)
                *(__half2*)&g_xwh[(row + 8) * NF + col] =
                    __floats2half2_rn(acc[mt][nt][2], acc[mt][nt][3]);
        }
    }
}

// ---------------- aggregation: warp per node, CSR gather (fp16), fp32 accum ----
// Always writes fp16 g_A (feeds next GEMM, or the pool for the last layer).
__global__ __launch_bounds__(256) void aggregate_kernel(const float* __restrict__ bias)
{
    int node = (blockIdx.x * blockDim.x + threadIdx.x) >> 5;
    if (node >= N_NODES) return;
    int lane = threadIdx.x & 31;
    int beg = g_rowptr[node];
    int end = g_rowptr[node + 1];
    float ax = 0.f, ay = 0.f, az = 0.f, aw = 0.f;
    int col = lane * 4;
    int e = beg;
    for (; e + 3 < end; e += 4) {                 // 4 gather rows in flight
        int2  ed[4];
        uint2 u[4];
        #pragma unroll
        for (int j = 0; j < 4; j++) ed[j] = g_edge[e + j];
        #pragma unroll
        for (int j = 0; j < 4; j++) u[j] = *(const uint2*)&g_xwh[ed[j].x * NF + col];
        #pragma unroll
        for (int j = 0; j < 4; j++) {
            float w = __int_as_float(ed[j].y);
            float2 f0 = __half22float2(*(__half2*)&u[j].x);
            float2 f1 = __half22float2(*(__half2*)&u[j].y);
            ax += w * f0.x; ay += w * f0.y; az += w * f1.x; aw += w * f1.y;
        }
    }
    for (; e < end; e++) {
        int2 ed = g_edge[e];
        uint2 u = *(const uint2*)&g_xwh[ed.x * NF + col];
        float w = __int_as_float(ed.y);
        float2 f0 = __half22float2(*(__half2*)&u.x);
        float2 f1 = __half22float2(*(__half2*)&u.y);
        ax += w * f0.x; ay += w * f0.y; az += w * f1.x; aw += w * f1.y;
    }
    float sd = g_invdeg[node];
    {
        uint2 u = *(const uint2*)&g_xwh[node * NF + col];
        float2 f0 = __half22float2(*(__half2*)&u.x);
        float2 f1 = __half22float2(*(__half2*)&u.y);
        ax += sd * f0.x; ay += sd * f0.y; az += sd * f1.x; aw += sd * f1.y;
    }
    float4 b = *(const float4*)&bias[col];
    ax = fmaxf(ax + b.x, 0.f);
    ay = fmaxf(ay + b.y, 0.f);
    az = fmaxf(az + b.z, 0.f);
    aw = fmaxf(aw + b.w, 0.f);
    *(__half2*)&g_A[node * NF + col + 0] = __floats2half2_rn(ax, ay);
    *(__half2*)&g_A[node * NF + col + 2] = __floats2half2_rn(az, aw);
}

// ---------------- pooling + FC ----------------
__global__ void graph_bounds_kernel(const void* __restrict__ batch) {
    bool is64 = (g_is64 != 0);
    int g = blockIdx.x * blockDim.x + threadIdx.x;
    if (g > N_GRAPHS) return;
    int lo = 0, hi = N_NODES;
    while (lo < hi) {
        int mid = (lo + hi) >> 1;
        int bv = load_idx(batch, mid, is64);
        if (bv < g) lo = mid + 1; else hi = mid;
    }
    g_gstart[g] = lo;
}

__global__ void pool_fc_kernel(const float* __restrict__ Wfc,
                               const float* __restrict__ bfc,
                               float* __restrict__ out)
{
    __shared__ float red[128];
    int g = blockIdx.x;
    int t = threadIdx.x;
    int beg = g_gstart[g], end = g_gstart[g + 1];
    if (beg < 0) beg = 0;
    if (end > N_NODES) end = N_NODES;
    float s = 0.f;
    for (int n = beg; n < end; n++)
        s += __half2float(g_A[n * NF + t]);
    float cnt = (float)(end - beg);
    float mean = (cnt > 0.f) ? (s / cnt) : 0.f;
    red[t] = mean * Wfc[t];
    __syncthreads();
    #pragma unroll
    for (int o = 64; o > 0; o >>= 1) {
        if (t < o) red[t] += red[t + o];
        __syncthreads();
    }
    if (t == 0) out[g] = red[0] + bfc[0];
}

// ---------------- launch ----------------
extern "C" void kernel_launch(void* const* d_in, const int* in_sizes, int n_in,
                              void* d_out, int out_size) {
    const float* x     = (const float*)d_in[0];
    const void*  ei    = d_in[1];
    const void*  batch = d_in[2];
    const float* W1  = (const float*)d_in[3];
    const float* b1  = (const float*)d_in[4];
    const float* W2  = (const float*)d_in[5];
    const float* b2  = (const float*)d_in[6];
    const float* W3  = (const float*)d_in[7];
    const float* b3  = (const float*)d_in[8];
    const float* Wfc = (const float*)d_in[9];
    const float* bfc = (const float*)d_in[10];
    float* out = (float*)d_out;

    // Fork a side stream for the CSR build (independent of converts + GEMM-1).
    cudaStream_t s2;
    cudaEvent_t evFork, evJoin;
    cudaStreamCreateWithFlags(&s2, cudaStreamNonBlocking);
    cudaEventCreateWithFlags(&evFork, cudaEventDisableTiming);
    cudaEventCreateWithFlags(&evJoin, cudaEventDisableTiming);

    cudaEventRecord(evFork, 0);
    cudaStreamWaitEvent(s2, evFork, 0);

    // branch B (s2): CSR build + graph bounds
    init_kernel<<<(N_NODES + 255) / 256, 256, 0, s2>>>((const int*)ei);
    count_deg_kernel<<<2048, 256, 0, s2>>>(ei);
    compute_isq_kernel<<<(N_NODES + 255) / 256, 256, 0, s2>>>();
    scan_kernel<<<1, 1024, 0, s2>>>();
    scatter_edges_kernel<<<2048, 256, 0, s2>>>(ei);
    graph_bounds_kernel<<<(N_GRAPHS + 1 + 255) / 256, 256, 0, s2>>>(batch);
    cudaEventRecord(evJoin, s2);

    // branch A (default stream): converts + layer-1 GEMM
    convert_w_kernel<<<(3 * NF * NF + 255) / 256, 256>>>(W1, W2, W3);
    convert_x_kernel<<<(N_NODES * NF / 4 + 255) / 256, 256>>>(x);

    dim3 gemm_grid((N_NODES + 127) / 128, 2);
    const int AGG_BLOCKS = (N_NODES * 32 + 255) / 256;

    gemm_f16_kernel<<<gemm_grid, 256>>>(0, N_NODES);

    // join: aggregation needs the CSR
    cudaStreamWaitEvent(0, evJoin, 0);

    aggregate_kernel<<<AGG_BLOCKS, 256>>>(b1);
    // layer 2
    gemm_f16_kernel<<<gemm_grid, 256>>>(1, N_NODES);
    aggregate_kernel<<<AGG_BLOCKS, 256>>>(b2);
    // layer 3
    gemm_f16_kernel<<<gemm_grid, 256>>>(2, N_NODES);
    aggregate_kernel<<<AGG_BLOCKS, 256>>>(b3);

    // pool + fc (reads fp16 g_A)
    pool_fc_kernel<<<N_GRAPHS, 128>>>(Wfc, bfc, out);
}

// round 17
// speedup vs baseline: 2.1750x; 1.1201x over previous
#include <cuda_runtime.h>
#include <cuda_bf16.h>
#include <cuda_fp16.h>
#include <math.h>

#define N_NODES   100000
#define N_EDGES   1600000
#define NF        128
#define N_GRAPHS  1024
#define SCAN_BLK  1024
#define SCAN_NB   ((N_NODES + SCAN_BLK - 1) / SCAN_BLK)   // 98

// ---------------- scratch (static device globals; no allocation) ----------------
__device__ __half g_xwh[N_NODES * NF];   // GEMM output (per-layer, fp16)
__device__ __half g_A  [N_NODES * NF];   // GEMM A input / final hidden (fp16)
__device__ __half g_Wh [3 * NF * NF];    // W transposed [layer][n][k], fp16 hi
__device__ __half g_Wl [3 * NF * NF];    // fp16 residual
__device__ int   g_cnt   [N_NODES];
__device__ int   g_rowptr[N_NODES + 1];
__device__ int   g_cursor[N_NODES];
__device__ int   g_bsum  [SCAN_NB];
__device__ int   g_boff  [SCAN_NB];
__device__ float g_isq   [N_NODES];
__device__ float g_invdeg[N_NODES];
__device__ int2  g_edge  [N_EDGES];      // {src, norm-as-int} packed
__device__ int   g_gstart[N_GRAPHS + 1];
__device__ int   g_is64;

// ---------------- init: dtype detect + zero counts (fused) ----------------
__global__ void init_kernel(const int* __restrict__ ei32) {
    int i = blockIdx.x * blockDim.x + threadIdx.x;
    if (i < N_NODES) g_cnt[i] = 0;
    if (i == 0) {
        int is64 = 1;
        #pragma unroll 1
        for (int k = 0; k < 128; k++) {
            if (ei32[2 * k + 1] != 0) { is64 = 0; break; }
        }
        g_is64 = is64;
    }
}

__device__ __forceinline__ int load_idx(const void* p, long long i, bool is64) {
    return is64 ? (int)((const long long*)p)[i] : ((const int*)p)[i];
}

// ---------------- CSR build ----------------
// two edges per thread, vectorized dst loads
__global__ void count_deg_kernel(const void* __restrict__ ei) {
    bool is64 = (g_is64 != 0);
    int stride = gridDim.x * blockDim.x;
    const int half = N_EDGES / 2;            // N_EDGES even
    if (is64) {
        const ulonglong2* dst2 = (const ulonglong2*)((const long long*)ei + N_EDGES);
        for (int e = blockIdx.x * blockDim.x + threadIdx.x; e < half; e += stride) {
            ulonglong2 d = dst2[e];
            int d0 = (int)d.x, d1 = (int)d.y;
            if ((unsigned)d0 < (unsigned)N_NODES) atomicAdd(&g_cnt[d0], 1);
            if ((unsigned)d1 < (unsigned)N_NODES) atomicAdd(&g_cnt[d1], 1);
        }
    } else {
        const int2* dst2 = (const int2*)((const int*)ei + N_EDGES);
        for (int e = blockIdx.x * blockDim.x + threadIdx.x; e < half; e += stride) {
            int2 d = dst2[e];
            if ((unsigned)d.x < (unsigned)N_NODES) atomicAdd(&g_cnt[d.x], 1);
            if ((unsigned)d.y < (unsigned)N_NODES) atomicAdd(&g_cnt[d.y], 1);
        }
    }
}

__global__ void compute_isq_kernel() {
    int i = blockIdx.x * blockDim.x + threadIdx.x;
    if (i >= N_NODES) return;
    float deg = (float)(g_cnt[i] + 1);
    g_isq[i]    = rsqrtf(deg);
    g_invdeg[i] = 1.0f / deg;
}

// ---- multi-block exclusive scan (3 phases) ----
// phase 1: block-local exclusive scan; local result -> g_rowptr, totals -> g_bsum
__global__ __launch_bounds__(SCAN_BLK) void scan_blocks_kernel() {
    __shared__ int wsum[32];
    int i = blockIdx.x * SCAN_BLK + threadIdx.x;
    int lane = threadIdx.x & 31, wid = threadIdx.x >> 5;
    int v = (i < N_NODES) ? g_cnt[i] : 0;
    int x = v;
    #pragma unroll
    for (int o = 1; o < 32; o <<= 1) {
        int y = __shfl_up_sync(0xffffffffu, x, o);
        if (lane >= o) x += y;
    }
    if (lane == 31) wsum[wid] = x;
    __syncthreads();
    if (wid == 0) {
        int s = wsum[lane];
        #pragma unroll
        for (int o = 1; o < 32; o <<= 1) {
            int y = __shfl_up_sync(0xffffffffu, s, o);
            if (lane >= o) s += y;
        }
        wsum[lane] = s;
    }
    __syncthreads();
    int excl = x - v + (wid ? wsum[wid - 1] : 0);
    if (i < N_NODES) g_rowptr[i] = excl;          // local-exclusive, pre-offset
    if (threadIdx.x == SCAN_BLK - 1) g_bsum[blockIdx.x] = excl + v;
}

// phase 2: exclusive-scan the SCAN_NB block sums (single block)
__global__ void scan_sums_kernel() {
    __shared__ int wsum[32];
    int lane = threadIdx.x & 31, wid = threadIdx.x >> 5;
    int v = (threadIdx.x < SCAN_NB) ? g_bsum[threadIdx.x] : 0;
    int x = v;
    #pragma unroll
    for (int o = 1; o < 32; o <<= 1) {
        int y = __shfl_up_sync(0xffffffffu, x, o);
        if (lane >= o) x += y;
    }
    if (lane == 31) wsum[wid] = x;
    __syncthreads();
    if (wid == 0) {
        int s = wsum[lane];
        #pragma unroll
        for (int o = 1; o < 32; o <<= 1) {
            int y = __shfl_up_sync(0xffffffffu, s, o);
            if (lane >= o) s += y;
        }
        wsum[lane] = s;
    }
    __syncthreads();
    int excl = x - v + (wid ? wsum[wid - 1] : 0);
    if (threadIdx.x < SCAN_NB) g_boff[threadIdx.x] = excl;
    if (threadIdx.x == 127) g_rowptr[N_NODES] = excl + v;   // total (SCAN_NB<=128)
}

// phase 3: add block offsets, emit final rowptr + cursor
__global__ __launch_bounds__(SCAN_BLK) void scan_apply_kernel() {
    int i = blockIdx.x * SCAN_BLK + threadIdx.x;
    if (i >= N_NODES) return;
    int r = g_rowptr[i] + g_boff[blockIdx.x];
    g_rowptr[i] = r;
    g_cursor[i] = r;
}

__global__ void scatter_edges_kernel(const void* __restrict__ ei) {
    bool is64 = (g_is64 != 0);
    int stride = gridDim.x * blockDim.x;
    for (int e = blockIdx.x * blockDim.x + threadIdx.x; e < N_EDGES; e += stride) {
        int src = load_idx(ei, e, is64);
        int dst = load_idx(ei, (long long)N_EDGES + e, is64);
        if ((unsigned)src >= (unsigned)N_NODES) continue;
        if ((unsigned)dst >= (unsigned)N_NODES) continue;
        int pos = atomicAdd(&g_cursor[dst], 1);
        if ((unsigned)pos < (unsigned)N_EDGES) {
            float nrm = g_isq[src] * g_isq[dst];
            g_edge[pos] = make_int2(src, __float_as_int(nrm));
        }
    }
}

// ---------------- converts ----------------
__global__ void convert_w_kernel(const float* __restrict__ W1,
                                 const float* __restrict__ W2,
                                 const float* __restrict__ W3) {
    int i = blockIdx.x * blockDim.x + threadIdx.x;
    if (i >= 3 * NF * NF) return;
    int layer = i / (NF * NF);
    int r = i % (NF * NF);
    int n = r / NF, k = r % NF;
    const float* W = (layer == 0) ? W1 : (layer == 1 ? W2 : W3);
    float w = W[k * NF + n];
    __half h = __float2half_rn(w);
    __half l = __float2half_rn(w - __half2float(h));
    g_Wh[i] = h;
    g_Wl[i] = l;
}

__global__ void convert_x_kernel(const float* __restrict__ x) {
    int i = blockIdx.x * blockDim.x + threadIdx.x;
    if (i * 4 >= N_NODES * NF) return;
    float4 v = ((const float4*)x)[i];
    *(__half2*)&g_A[i * 4 + 0] = __floats2half2_rn(v.x, v.y);
    *(__half2*)&g_A[i * 4 + 2] = __floats2half2_rn(v.z, v.w);
}

// ---------------- tensor-core GEMM ----------------
// g_xwh[M x 128] = A @ (Wh+Wl)   (A fp16, W fp16-split, fp32 accum, fp16 out).
// Block tile 128m x 64n (grid.y=2), 8 warps 4x2; warp 32m x 32n.
// SPAD=40 (80 B rows): ldmatrix phases conflict-free, 16 B alignment preserved.
#define SPAD 40

#define LDSM4(r, addr) asm volatile( \
    "ldmatrix.sync.aligned.m8n8.x4.shared.b16 {%0,%1,%2,%3}, [%4];" \
    : "=r"((r)[0]), "=r"((r)[1]), "=r"((r)[2]), "=r"((r)[3]) : "r"(addr))

#define MMA16816F16(d, a, b) asm volatile( \
    "mma.sync.aligned.m16n8k16.row.col.f32.f16.f16.f32 " \
    "{%0,%1,%2,%3}, {%4,%5,%6,%7}, {%8,%9}, {%0,%1,%2,%3};" \
    : "+f"((d)[0]), "+f"((d)[1]), "+f"((d)[2]), "+f"((d)[3]) \
    : "r"((a)[0]), "r"((a)[1]), "r"((a)[2]), "r"((a)[3]), \
      "r"((b)[0]), "r"((b)[1]))

__global__ __launch_bounds__(256) void gemm_f16_kernel(int layer, int M)
{
    __shared__ __align__(16) __half sA [128 * SPAD];
    __shared__ __align__(16) __half sBh[64 * SPAD];
    __shared__ __align__(16) __half sBl[64 * SPAD];

    int tid  = threadIdx.x;
    int lane = tid & 31;
    int wid  = tid >> 5;
    int m0b  = blockIdx.x * 128;
    int n0b  = blockIdx.y * 64;
    int wm   = (wid & 3) * 32;
    int wn   = (wid >> 2) * 32;
    const __half* Wh = g_Wh + layer * NF * NF;
    const __half* Wl = g_Wl + layer * NF * NF;

    unsigned sA_u  = (unsigned)__cvta_generic_to_shared(sA);
    unsigned sBh_u = (unsigned)__cvta_generic_to_shared(sBh);
    unsigned sBl_u = (unsigned)__cvta_generic_to_shared(sBl);

    int a_row = lane & 15;
    int a_k   = (lane >> 4) << 3;
    int b_row = ((lane >> 4) << 3) + (lane & 7);
    int b_k   = ((lane >> 3) & 1) << 3;

    float acc[2][4][4];
    #pragma unroll
    for (int mt = 0; mt < 2; mt++)
        #pragma unroll
        for (int nt = 0; nt < 4; nt++)
            #pragma unroll
            for (int c = 0; c < 4; c++) acc[mt][nt][c] = 0.f;

    #pragma unroll 1
    for (int kc = 0; kc < 4; kc++) {
        __syncthreads();
        #pragma unroll
        for (int it = 0; it < 2; it++) {
            int f = tid + it * 256;
            int r = f >> 2;
            int gq = (f & 3) * 8;
            int row = m0b + r;
            uint4 va = make_uint4(0, 0, 0, 0);
            if (row < M) va = *(const uint4*)&g_A[row * NF + kc * 32 + gq];
            *(uint4*)&sA[r * SPAD + gq] = va;
        }
        {
            int r = tid >> 2;
            int gq = (tid & 3) * 8;
            *(uint4*)&sBh[r * SPAD + gq] = *(const uint4*)&Wh[(n0b + r) * NF + kc * 32 + gq];
            *(uint4*)&sBl[r * SPAD + gq] = *(const uint4*)&Wl[(n0b + r) * NF + kc * 32 + gq];
        }
        __syncthreads();

        #pragma unroll
        for (int ks = 0; ks < 2; ks++) {
            int kk = ks * 16;
            unsigned aF[2][4], bH[4][2], bL[4][2];
            #pragma unroll
            for (int mt = 0; mt < 2; mt++) {
                unsigned off = (unsigned)(((wm + mt * 16 + a_row) * SPAD + kk + a_k) * 2);
                LDSM4(aF[mt], sA_u + off);
            }
            #pragma unroll
            for (int np = 0; np < 2; np++) {
                unsigned off = (unsigned)(((wn + np * 16 + b_row) * SPAD + kk + b_k) * 2);
                unsigned th[4], tl[4];
                LDSM4(th, sBh_u + off);
                LDSM4(tl, sBl_u + off);
                bH[np * 2 + 0][0] = th[0]; bH[np * 2 + 0][1] = th[1];
                bH[np * 2 + 1][0] = th[2]; bH[np * 2 + 1][1] = th[3];
                bL[np * 2 + 0][0] = tl[0]; bL[np * 2 + 0][1] = tl[1];
                bL[np * 2 + 1][0] = tl[2]; bL[np * 2 + 1][1] = tl[3];
            }
            #pragma unroll
            for (int mt = 0; mt < 2; mt++)
                #pragma unroll
                for (int nt = 0; nt < 4; nt++) {
                    MMA16816F16(acc[mt][nt], aF[mt], bH[nt]);
                    MMA16816F16(acc[mt][nt], aF[mt], bL[nt]);
                }
        }
    }

    #pragma unroll
    for (int mt = 0; mt < 2; mt++) {
        #pragma unroll
        for (int nt = 0; nt < 4; nt++) {
            int row = m0b + wm + mt * 16 + (lane >> 2);
            int col = n0b + wn + nt * 8 + (lane & 3) * 2;
            if (row < M)
                *(__half2*)&g_xwh[row * NF + col] =
                    __floats2half2_rn(acc[mt][nt][0], acc[mt][nt][1]);
            if (row + 8 < M)
                *(__half2*)&g_xwh[(row + 8) * NF + col] =
                    __floats2half2_rn(acc[mt][nt][2], acc[mt][nt][3]);
        }
    }
}

// ---------------- aggregation: warp per node, CSR gather (fp16), fp32 accum ----
__global__ __launch_bounds__(256) void aggregate_kernel(const float* __restrict__ bias)
{
    int node = (blockIdx.x * blockDim.x + threadIdx.x) >> 5;
    if (node >= N_NODES) return;
    int lane = threadIdx.x & 31;
    int beg = g_rowptr[node];
    int end = g_rowptr[node + 1];
    float ax = 0.f, ay = 0.f, az = 0.f, aw = 0.f;
    int col = lane * 4;
    int e = beg;
    for (; e + 3 < end; e += 4) {                 // 4 gather rows in flight
        int2  ed[4];
        uint2 u[4];
        #pragma unroll
        for (int j = 0; j < 4; j++) ed[j] = g_edge[e + j];
        #pragma unroll
        for (int j = 0; j < 4; j++) u[j] = *(const uint2*)&g_xwh[ed[j].x * NF + col];
        #pragma unroll
        for (int j = 0; j < 4; j++) {
            float w = __int_as_float(ed[j].y);
            float2 f0 = __half22float2(*(__half2*)&u[j].x);
            float2 f1 = __half22float2(*(__half2*)&u[j].y);
            ax += w * f0.x; ay += w * f0.y; az += w * f1.x; aw += w * f1.y;
        }
    }
    for (; e < end; e++) {
        int2 ed = g_edge[e];
        uint2 u = *(const uint2*)&g_xwh[ed.x * NF + col];
        float w = __int_as_float(ed.y);
        float2 f0 = __half22float2(*(__half2*)&u.x);
        float2 f1 = __half22float2(*(__half2*)&u.y);
        ax += w * f0.x; ay += w * f0.y; az += w * f1.x; aw += w * f1.y;
    }
    float sd = g_invdeg[node];
    {
        uint2 u = *(const uint2*)&g_xwh[node * NF + col];
        float2 f0 = __half22float2(*(__half2*)&u.x);
        float2 f1 = __half22float2(*(__half2*)&u.y);
        ax += sd * f0.x; ay += sd * f0.y; az += sd * f1.x; aw += sd * f1.y;
    }
    float4 b = *(const float4*)&bias[col];
    ax = fmaxf(ax + b.x, 0.f);
    ay = fmaxf(ay + b.y, 0.f);
    az = fmaxf(az + b.z, 0.f);
    aw = fmaxf(aw + b.w, 0.f);
    *(__half2*)&g_A[node * NF + col + 0] = __floats2half2_rn(ax, ay);
    *(__half2*)&g_A[node * NF + col + 2] = __floats2half2_rn(az, aw);
}

// ---------------- pooling + FC ----------------
__global__ void graph_bounds_kernel(const void* __restrict__ batch) {
    bool is64 = (g_is64 != 0);
    int g = blockIdx.x * blockDim.x + threadIdx.x;
    if (g > N_GRAPHS) return;
    int lo = 0, hi = N_NODES;
    while (lo < hi) {
        int mid = (lo + hi) >> 1;
        int bv = load_idx(batch, mid, is64);
        if (bv < g) lo = mid + 1; else hi = mid;
    }
    g_gstart[g] = lo;
}

__global__ void pool_fc_kernel(const float* __restrict__ Wfc,
                               const float* __restrict__ bfc,
                               float* __restrict__ out)
{
    __shared__ float red[128];
    int g = blockIdx.x;
    int t = threadIdx.x;
    int beg = g_gstart[g], end = g_gstart[g + 1];
    if (beg < 0) beg = 0;
    if (end > N_NODES) end = N_NODES;
    float s = 0.f;
    for (int n = beg; n < end; n++)
        s += __half2float(g_A[n * NF + t]);
    float cnt = (float)(end - beg);
    float mean = (cnt > 0.f) ? (s / cnt) : 0.f;
    red[t] = mean * Wfc[t];
    __syncthreads();
    #pragma unroll
    for (int o = 64; o > 0; o >>= 1) {
        if (t < o) red[t] += red[t + o];
        __syncthreads();
    }
    if (t == 0) out[g] = red[0] + bfc[0];
}

// ---------------- launch ----------------
extern "C" void kernel_launch(void* const* d_in, const int* in_sizes, int n_in,
                              void* d_out, int out_size) {
    const float* x     = (const float*)d_in[0];
    const void*  ei    = d_in[1];
    const void*  batch = d_in[2];
    const float* W1  = (const float*)d_in[3];
    const float* b1  = (const float*)d_in[4];
    const float* W2  = (const float*)d_in[5];
    const float* b2  = (const float*)d_in[6];
    const float* W3  = (const float*)d_in[7];
    const float* b3  = (const float*)d_in[8];
    const float* Wfc = (const float*)d_in[9];
    const float* bfc = (const float*)d_in[10];
    float* out = (float*)d_out;

    // Fork a side stream for the CSR build (independent of converts + GEMM-1).
    cudaStream_t s2;
    cudaEvent_t evFork, evJoin;
    cudaStreamCreateWithFlags(&s2, cudaStreamNonBlocking);
    cudaEventCreateWithFlags(&evFork, cudaEventDisableTiming);
    cudaEventCreateWithFlags(&evJoin, cudaEventDisableTiming);

    cudaEventRecord(evFork, 0);
    cudaStreamWaitEvent(s2, evFork, 0);

    // branch B (s2): CSR build + graph bounds
    init_kernel<<<(N_NODES + 255) / 256, 256, 0, s2>>>((const int*)ei);
    count_deg_kernel<<<2048, 256, 0, s2>>>(ei);
    compute_isq_kernel<<<(N_NODES + 255) / 256, 256, 0, s2>>>();
    scan_blocks_kernel<<<SCAN_NB, SCAN_BLK, 0, s2>>>();
    scan_sums_kernel<<<1, 128, 0, s2>>>();
    scan_apply_kernel<<<SCAN_NB, SCAN_BLK, 0, s2>>>();
    scatter_edges_kernel<<<2048, 256, 0, s2>>>(ei);
    graph_bounds_kernel<<<(N_GRAPHS + 1 + 255) / 256, 256, 0, s2>>>(batch);
    cudaEventRecord(evJoin, s2);

    // branch A (default stream): converts + layer-1 GEMM
    convert_w_kernel<<<(3 * NF * NF + 255) / 256, 256>>>(W1, W2, W3);
    convert_x_kernel<<<(N_NODES * NF / 4 + 255) / 256, 256>>>(x);

    dim3 gemm_grid((N_NODES + 127) / 128, 2);
    const int AGG_BLOCKS = (N_NODES * 32 + 255) / 256;

    gemm_f16_kernel<<<gemm_grid, 256>>>(0, N_NODES);

    // join: aggregation needs the CSR
    cudaStreamWaitEvent(0, evJoin, 0);

    aggregate_kernel<<<AGG_BLOCKS, 256>>>(b1);
    // layer 2
    gemm_f16_kernel<<<gemm_grid, 256>>>(1, N_NODES);
    aggregate_kernel<<<AGG_BLOCKS, 256>>>(b2);
    // layer 3
    gemm_f16_kernel<<<gemm_grid, 256>>>(2, N_NODES);
    aggregate_kernel<<<AGG_BLOCKS, 256>>>(b3);

    // pool + fc (reads fp16 g_A)
    pool_fc_kernel<<<N_GRAPHS, 128>>>(Wfc, bfc, out);
}